// round 10
// baseline (speedup 1.0000x reference)
#include <cuda_runtime.h>
#include <cuda_bf16.h>
#include <math.h>
#include <stdint.h>

// ---------------- problem constants ----------------
#define VV_  50000
#define EXTV_ 50400

// output offsets (flattened tuple order)
#define OFF_FD  0
#define OFF_H   25804800
#define OFF_C   25935872
#define OFF_CT1 26066944
#define OFF_CT2 26329088
#define OFF_PG  26591232
#define OFF_COV 26591744
#define OUT_FULL 26657280

// ---------------- device scratch (no cudaMalloc allowed) ----------------
__device__ float g_qk[65536 * 1024];            // Q | K per enc position (fp32)
__device__ __nv_bfloat16 g_A3[(size_t)65536 * 1536];  // [ah | ah | al] concat, K'=1536
__device__ __nv_bfloat16 g_B3[1024 * 1536];           // [bh | bl | bh] concat
__device__ float g_wgT[384 * 1024];
__device__ float g_xcWT[640 * 128];
__device__ float g_o1WT[768 * 256];
__device__ float g_wvT[512 * 512];
__device__ float g_woT[512 * 512];
__device__ float g_o2WT[256 * 50000];
__device__ float g_cat1[512 * 640];
__device__ float g_x[512 * 128];
__device__ float g_cat2[512 * 384];
__device__ float g_gates[512 * 1024];
__device__ float g_h[512 * 256];
__device__ float g_c[512 * 256];
__device__ float g_e[512 * 8 * 512];
__device__ float g_pooled[512 * 512];
__device__ float g_ct[512 * 512];
__device__ float g_cat3[512 * 768];
__device__ float g_out1[512 * 256];
__device__ float g_pgen[512];
__device__ float g_Z[512];

__device__ __forceinline__ float sigmoidf_(float x) { return 1.0f / (1.0f + __expf(-x)); }

__device__ __forceinline__ uint32_t smem_u32_(const void* p) {
    uint32_t a;
    asm("{ .reg .u64 t; cvta.to.shared.u64 t, %1; cvt.u32.u64 %0, t; }" : "=r"(a) : "l"(p));
    return a;
}

__device__ __forceinline__ void cp_async16_(uint32_t dst, const void* src) {
    asm volatile("cp.async.cg.shared.global [%0], [%1], 16;" :: "r"(dst), "l"(src));
}

// ---------------- split-3 concat prep ----------------
__global__ void buildA3_k(const float* __restrict__ enc, __nv_bfloat16* __restrict__ A) {
    int i = blockIdx.x * 256 + threadIdx.x;
    if (i >= 65536 * 512) return;
    int r = i >> 9, k = i & 511;
    float v = enc[i];
    __nv_bfloat16 h = __float2bfloat16(v);
    __nv_bfloat16 lo = __float2bfloat16(v - __bfloat162float(h));
    size_t base = (size_t)r * 1536;
    A[base + k] = h;
    A[base + 512 + k] = h;
    A[base + 1024 + k] = lo;
}

__global__ void buildB3_k(const float* __restrict__ Wq, const float* __restrict__ Wk,
                          __nv_bfloat16* __restrict__ B) {
    int i = blockIdx.x * 256 + threadIdx.x;
    if (i >= 1024 * 512) return;
    int n = i >> 9, k = i & 511;
    float v = (n < 512) ? Wq[(size_t)n * 512 + k] : Wk[(size_t)(n - 512) * 512 + k];
    __nv_bfloat16 h = __float2bfloat16(v);
    __nv_bfloat16 lo = __float2bfloat16(v - __bfloat162float(h));
    size_t base = (size_t)n * 1536;
    B[base + k] = h;
    B[base + 512 + k] = lo;
    B[base + 1024 + k] = h;
}

// ---------------- bf16 HMMA GEMM with 2-stage cp.async pipeline ----------------
// C[65536,1024] = A'[.,1536] @ B'[.,1536]^T ; block tile 128x128, warp tile 64x32
// dynamic smem: A [2][128][72] bf16, then B [2][128][72] bf16  (73728 bytes)
// __launch_bounds__(256, 2): cap regs at 128 so 2 CTAs fit the 64K regfile/SM
#define QK_SMEM (4 * 128 * 72 * 2)
__global__ __launch_bounds__(256, 2) void qk_mma_k(const __nv_bfloat16* __restrict__ A,
                                                   const __nv_bfloat16* __restrict__ B,
                                                   float* __restrict__ C) {
    extern __shared__ __nv_bfloat16 smem_bf[];
    const int tid = threadIdx.x;
    const int wid = tid >> 5, lane = tid & 31;
    const int wm = (wid & 1) << 6;
    const int wn = (wid >> 1) << 5;
    const int m0 = blockIdx.y << 7;
    const int n0 = blockIdx.x << 7;
    const int lr = lane & 7;
    const int lg = lane >> 3;

    const int r_ld[4] = { tid >> 3, (tid + 256) >> 3, (tid + 512) >> 3, (tid + 768) >> 3 };
    const int c8_ld = (tid & 7) << 3;

    float acc[4][4][4];
#pragma unroll
    for (int mi = 0; mi < 4; mi++)
#pragma unroll
        for (int ni = 0; ni < 4; ni++)
#pragma unroll
            for (int r = 0; r < 4; r++) acc[mi][ni][r] = 0.f;

#pragma unroll
    for (int i = 0; i < 4; i++) {
        int r = r_ld[i];
        cp_async16_(smem_u32_(&smem_bf[r * 72 + c8_ld]),
                    A + (size_t)(m0 + r) * 1536 + c8_ld);
        cp_async16_(smem_u32_(&smem_bf[18432 + r * 72 + c8_ld]),
                    B + (size_t)(n0 + r) * 1536 + c8_ld);
    }
    asm volatile("cp.async.commit_group;" ::: "memory");

    for (int kt = 0; kt < 24; kt++) {
        const int buf = kt & 1;
        if (kt < 23) {
            const int nb = (kt + 1) & 1;
            const int kof = (kt + 1) << 6;
#pragma unroll
            for (int i = 0; i < 4; i++) {
                int r = r_ld[i];
                cp_async16_(smem_u32_(&smem_bf[nb * 9216 + r * 72 + c8_ld]),
                            A + (size_t)(m0 + r) * 1536 + kof + c8_ld);
                cp_async16_(smem_u32_(&smem_bf[18432 + nb * 9216 + r * 72 + c8_ld]),
                            B + (size_t)(n0 + r) * 1536 + kof + c8_ld);
            }
            asm volatile("cp.async.commit_group;" ::: "memory");
            asm volatile("cp.async.wait_group 1;" ::: "memory");
        } else {
            asm volatile("cp.async.wait_group 0;" ::: "memory");
        }
        __syncthreads();

        const __nv_bfloat16* bufA = smem_bf + buf * 9216;
        const __nv_bfloat16* bufB = smem_bf + 18432 + buf * 9216;
#pragma unroll
        for (int ks = 0; ks < 4; ks++) {
            uint32_t af[4][4];
#pragma unroll
            for (int mi = 0; mi < 4; mi++) {
                uint32_t addr = smem_u32_(
                    bufA + (wm + (mi << 4) + lr + ((lg & 1) << 3)) * 72 + (ks << 4) + ((lg >> 1) << 3));
                asm volatile("ldmatrix.sync.aligned.m8n8.x4.shared.b16 {%0,%1,%2,%3}, [%4];"
                             : "=r"(af[mi][0]), "=r"(af[mi][1]), "=r"(af[mi][2]), "=r"(af[mi][3])
                             : "r"(addr));
            }
            uint32_t bfr[4][2];
#pragma unroll
            for (int ni = 0; ni < 4; ni++) {
                uint32_t addr = smem_u32_(
                    bufB + (wn + (ni << 3) + lr) * 72 + (ks << 4) + ((lg & 1) << 3));
                asm volatile("ldmatrix.sync.aligned.m8n8.x2.shared.b16 {%0,%1}, [%2];"
                             : "=r"(bfr[ni][0]), "=r"(bfr[ni][1])
                             : "r"(addr));
            }
#pragma unroll
            for (int mi = 0; mi < 4; mi++)
#pragma unroll
                for (int ni = 0; ni < 4; ni++) {
                    asm volatile(
                        "mma.sync.aligned.m16n8k16.row.col.f32.bf16.bf16.f32 "
                        "{%0,%1,%2,%3}, {%4,%5,%6,%7}, {%8,%9}, {%0,%1,%2,%3};"
                        : "+f"(acc[mi][ni][0]), "+f"(acc[mi][ni][1]),
                          "+f"(acc[mi][ni][2]), "+f"(acc[mi][ni][3])
                        : "r"(af[mi][0]), "r"(af[mi][1]), "r"(af[mi][2]), "r"(af[mi][3]),
                          "r"(bfr[ni][0]), "r"(bfr[ni][1]));
                }
        }
        __syncthreads();
    }

    const int er = lane >> 2;
    const int ec = (lane & 3) << 1;
#pragma unroll
    for (int mi = 0; mi < 4; mi++) {
#pragma unroll
        for (int ni = 0; ni < 4; ni++) {
            size_t row = (size_t)(m0 + wm + (mi << 4) + er);
            int col = n0 + wn + (ni << 3) + ec;
            *(float2*)&C[row * 1024 + col] = make_float2(acc[mi][ni][0], acc[mi][ni][1]);
            *(float2*)&C[(row + 8) * 1024 + col] = make_float2(acc[mi][ni][2], acc[mi][ni][3]);
        }
    }
}

// ---------------- single-pass register-tiled pooled attention ----------------
#define ATTN_SMEM ((128 * 65 + 64 * 128 + 16 * 128 + 128) * 4)
__global__ __launch_bounds__(256) void attn_pool2_k(const float* __restrict__ qk,
                                                    const float* __restrict__ enc) {
    extern __shared__ float sm[];
    float* Qh   = sm;
    float* KhT  = Qh + 128 * 65;
    float* part = KhT + 64 * 128;
    float* w    = part + 16 * 128;
    const int h = blockIdx.x, b = blockIdx.y;
    const int tid = threadIdx.x;
    const int tx = tid & 15, ty = tid >> 4;

    for (int i = tid; i < 2048; i += 256) {
        int r = i >> 4, c4 = (i & 15) << 2;
        float4 v = *(const float4*)(qk + ((size_t)(b * 128 + r)) * 1024 + h * 64 + c4);
        float* dst = Qh + r * 65 + c4;
        dst[0] = v.x; dst[1] = v.y; dst[2] = v.z; dst[3] = v.w;
        float4 u = *(const float4*)(qk + ((size_t)(b * 128 + r)) * 1024 + 512 + h * 64 + c4);
        KhT[(c4 + 0) * 128 + r] = u.x;
        KhT[(c4 + 1) * 128 + r] = u.y;
        KhT[(c4 + 2) * 128 + r] = u.z;
        KhT[(c4 + 3) * 128 + r] = u.w;
    }
    __syncthreads();

    float acc[8][8];
#pragma unroll
    for (int i = 0; i < 8; i++)
#pragma unroll
        for (int j = 0; j < 8; j++) acc[i][j] = 0.f;

    for (int k = 0; k < 64; k++) {
        float a[8], bb[8];
#pragma unroll
        for (int i = 0; i < 8; i++) a[i] = Qh[(ty + (i << 4)) * 65 + k];
#pragma unroll
        for (int j = 0; j < 8; j++) bb[j] = KhT[k * 128 + tx + (j << 4)];
#pragma unroll
        for (int i = 0; i < 8; i++)
#pragma unroll
            for (int j = 0; j < 8; j++) acc[i][j] = fmaf(a[i], bb[j], acc[i][j]);
    }

    float rs[8];
#pragma unroll
    for (int i = 0; i < 8; i++) {
        float s = 0.f;
#pragma unroll
        for (int j = 0; j < 8; j++) {
            float e = __expf(acc[i][j] * 0.125f);
            acc[i][j] = e;
            s += e;
        }
        rs[i] = s;
    }
#pragma unroll
    for (int m = 1; m < 16; m <<= 1)
#pragma unroll
        for (int i = 0; i < 8; i++) rs[i] += __shfl_xor_sync(0xffffffffu, rs[i], m);

    float cs[8];
#pragma unroll
    for (int j = 0; j < 8; j++) cs[j] = 0.f;
#pragma unroll
    for (int i = 0; i < 8; i++) {
        float zi = 1.f / rs[i];
#pragma unroll
        for (int j = 0; j < 8; j++) cs[j] = fmaf(acc[i][j], zi, cs[j]);
    }
#pragma unroll
    for (int j = 0; j < 8; j++) part[ty * 128 + tx + (j << 4)] = cs[j];
    __syncthreads();

    if (tid < 128) {
        float s = 0.f;
#pragma unroll
        for (int t2 = 0; t2 < 16; t2++) s += part[t2 * 128 + tid];
        w[tid] = s * (1.f / 128.f);
    }
    __syncthreads();

    float ea0 = 0.f, ea1 = 0.f;
    const float* encb = enc + (size_t)b * 128 * 512;
    for (int t = 0; t < 128; t++) {
        float wt = w[t];
        ea0 = fmaf(wt, encb[t * 512 + tid], ea0);
        ea1 = fmaf(wt, encb[t * 512 + tid + 256], ea1);
    }
    float* eo = g_e + ((size_t)b * 8 + h) * 512;
    eo[tid] = ea0;
    eo[tid + 256] = ea1;
}

// ---------------- weight prep kernels ----------------
__global__ void build_wgT_k(const float* __restrict__ Wih, const float* __restrict__ Whh) {
    int idx = blockIdx.x * 256 + threadIdx.x;
    if (idx >= 384 * 1024) return;
    int j = idx >> 10, r = idx & 1023;
    g_wgT[idx] = (j < 128) ? Wih[(size_t)r * 128 + j] : Whh[(size_t)r * 256 + (j - 128)];
}

__global__ void transpose_k(const float* __restrict__ in, float* __restrict__ out, int R, int C) {
    __shared__ float t[32][33];
    int c0 = blockIdx.x << 5, r0 = blockIdx.y << 5;
    int c = c0 + threadIdx.x;
    for (int i = threadIdx.y; i < 32; i += 8) {
        int r = r0 + i;
        if (r < R && c < C) t[i][threadIdx.x] = in[(size_t)r * C + c];
    }
    __syncthreads();
    int rr = r0 + threadIdx.x;
    for (int i = threadIdx.y; i < 32; i += 8) {
        int cc = c0 + i;
        if (cc < C && rr < R) out[(size_t)cc * R + rr] = t[threadIdx.x][i];
    }
}

// ---------------- concat builders ----------------
__global__ void cat1_k(const float* __restrict__ ct1, const float* __restrict__ embW,
                       const int* __restrict__ y) {
    int idx = blockIdx.x * 256 + threadIdx.x;
    if (idx >= 512 * 640) return;
    int b = idx / 640, j = idx - b * 640;
    g_cat1[idx] = (j < 512) ? ct1[(size_t)b * 512 + j]
                            : embW[(size_t)y[b] * 128 + (j - 512)];
}

__global__ void cat2_k(const float* __restrict__ h0) {
    int idx = blockIdx.x * 256 + threadIdx.x;
    if (idx >= 512 * 384) return;
    int b = idx / 384, j = idx - b * 384;
    g_cat2[idx] = (j < 128) ? g_x[b * 128 + j] : h0[(size_t)b * 256 + (j - 128)];
}

__global__ void cat3_k() {
    int idx = blockIdx.x * 256 + threadIdx.x;
    if (idx >= 512 * 768) return;
    int b = idx / 768, j = idx - b * 768;
    g_cat3[idx] = (j < 256) ? g_h[b * 256 + j] : g_ct[b * 512 + (j - 256)];
}

// ---------------- small dense ----------------
__global__ __launch_bounds__(256) void dense8_k(const float* __restrict__ X,
                                                const float* __restrict__ Wt,
                                                const float* __restrict__ b1,
                                                const float* __restrict__ b2,
                                                float* __restrict__ Y, int K, int N) {
    __shared__ float xs[8 * 768];
    const int tid = threadIdx.x;
    const int m0 = blockIdx.y << 3;
    const int col = (blockIdx.x << 8) + tid;
    for (int i = tid; i < (K << 3); i += 256) {
        int r = i / K, j = i - r * K;
        xs[i] = X[(size_t)(m0 + r) * K + j];
    }
    __syncthreads();
    if (col >= N) return;
    float acc[8];
#pragma unroll
    for (int r = 0; r < 8; r++) acc[r] = 0.f;
#pragma unroll 4
    for (int j = 0; j < K; j++) {
        float w = Wt[(size_t)j * N + col];
#pragma unroll
        for (int r = 0; r < 8; r++) acc[r] = fmaf(xs[r * K + j], w, acc[r]);
    }
    float bb = (b1 ? b1[col] : 0.f) + (b2 ? b2[col] : 0.f);
#pragma unroll
    for (int r = 0; r < 8; r++) Y[(size_t)(m0 + r) * N + col] = acc[r] + bb;
}

// ---------------- LSTM pointwise ----------------
__global__ void lstm_k(const float* __restrict__ c0, float* __restrict__ outH, float* __restrict__ outC) {
    int i = blockIdx.x * 256 + threadIdx.x;
    if (i >= 512 * 256) return;
    int b = i >> 8, u = i & 255;
    const float* g = &g_gates[b * 1024];
    float ig = sigmoidf_(g[u]);
    float fg = sigmoidf_(g[256 + u]);
    float gg = tanhf(g[512 + u]);
    float og = sigmoidf_(g[768 + u]);
    float cn = fg * c0[i] + ig * gg;
    float hn = og * tanhf(cn);
    g_h[i] = hn;
    g_c[i] = cn;
    if (outH) outH[i] = hn;
    if (outC) outC[i] = cn;
}

// ---------------- logits SGEMM fused with exp + row-sum ----------------
__global__ __launch_bounds__(256) void sgemm_logits(const float* __restrict__ A, const float* __restrict__ Bm,
                                                    const float* __restrict__ bias,
                                                    float* __restrict__ outE, int N, int K) {
    __shared__ float As[16][128];
    __shared__ float Bs[16][128];
    const int tid = threadIdx.x;
    const int tx = tid & 15, ty = tid >> 4;
    const int bm = blockIdx.y << 7, bn = blockIdx.x << 7;
    float acc[8][8];
#pragma unroll
    for (int i = 0; i < 8; i++)
#pragma unroll
        for (int j = 0; j < 8; j++) acc[i][j] = 0.f;

    for (int k0 = 0; k0 < K; k0 += 16) {
#pragma unroll
        for (int uu = 0; uu < 2; uu++) {
            int u = tid + (uu << 8);
            int r = u >> 2, kq = u & 3;
            float4 v = *reinterpret_cast<const float4*>(A + (size_t)(bm + r) * K + k0 + (kq << 2));
            As[(kq << 2) + 0][r] = v.x;
            As[(kq << 2) + 1][r] = v.y;
            As[(kq << 2) + 2][r] = v.z;
            As[(kq << 2) + 3][r] = v.w;
        }
#pragma unroll
        for (int uu = 0; uu < 2; uu++) {
            int u = tid + (uu << 8);
            int kr = u >> 5, nq = u & 31;
            int colb = bn + (nq << 2);
            const float* src = Bm + (size_t)(k0 + kr) * N;
            float4 v;
            if (colb + 3 < N) {
                v = *reinterpret_cast<const float4*>(src + colb);
            } else {
                v.x = (colb + 0 < N) ? src[colb + 0] : 0.f;
                v.y = (colb + 1 < N) ? src[colb + 1] : 0.f;
                v.z = (colb + 2 < N) ? src[colb + 2] : 0.f;
                v.w = (colb + 3 < N) ? src[colb + 3] : 0.f;
            }
            *reinterpret_cast<float4*>(&Bs[kr][nq << 2]) = v;
        }
        __syncthreads();
#pragma unroll
        for (int kk = 0; kk < 16; kk++) {
            float a[8], bv[8];
            *(float4*)&a[0] = *(const float4*)&As[kk][ty << 3];
            *(float4*)&a[4] = *(const float4*)&As[kk][(ty << 3) + 4];
            *(float4*)&bv[0] = *(const float4*)&Bs[kk][tx << 3];
            *(float4*)&bv[4] = *(const float4*)&Bs[kk][(tx << 3) + 4];
#pragma unroll
            for (int i = 0; i < 8; i++)
#pragma unroll
                for (int j = 0; j < 8; j++) acc[i][j] = fmaf(a[i], bv[j], acc[i][j]);
        }
        __syncthreads();
    }
#pragma unroll
    for (int i = 0; i < 8; i++) {
        int row = bm + (ty << 3) + i;
        float rs = 0.f;
        float* orow = outE + (size_t)row * EXTV_;
#pragma unroll
        for (int j = 0; j < 8; j++) {
            int col = bn + (tx << 3) + j;
            if (col < N) {
                float e = __expf(acc[i][j] + bias[col]);
                orow[col] = e;
                rs += e;
            }
        }
#pragma unroll
        for (int m = 1; m < 16; m <<= 1) rs += __shfl_xor_sync(0xffffffffu, rs, m);
        if (tx == 0) atomicAdd(&g_Z[row], rs);
    }
}

// ---------------- per-head Wv fold ----------------
__global__ __launch_bounds__(128) void wv_head_k() {
    __shared__ float es[8 * 2 * 512];
    const int tid = threadIdx.x;
    const int cx = blockIdx.x;
    const int b0 = blockIdx.y << 3;
    const int hbase = cx << 1;

    for (int i = tid; i < 8 * 2 * 512; i += 128) {
        int bb = i >> 10;
        int rem = i & 1023;
        int hh = rem >> 9;
        int j = rem & 511;
        es[i] = g_e[((size_t)(b0 + bb) * 8 + hbase + hh) * 512 + j];
    }
    __syncthreads();

    const int col = (cx << 7) + tid;
    const int hh = tid >> 6;
    float acc[8];
#pragma unroll
    for (int bb = 0; bb < 8; bb++) acc[bb] = 0.f;
    for (int j = 0; j < 512; j++) {
        float w0 = g_wvT[(size_t)j * 512 + col];
#pragma unroll
        for (int bb = 0; bb < 8; bb++)
            acc[bb] = fmaf(es[(bb << 10) + (hh << 9) + j], w0, acc[bb]);
    }
#pragma unroll
    for (int bb = 0; bb < 8; bb++)
        g_pooled[(size_t)(b0 + bb) * 512 + col] = acc[bb];
}

// ---------------- pointer gate ----------------
__global__ void pgen_k(const float* __restrict__ pgW, const float* __restrict__ pgb,
                       float* __restrict__ outPG) {
    int b = blockIdx.x;
    int tid = threadIdx.x;
    float s = 0.f;
    for (int j = tid; j < 1152; j += 128) {
        float v;
        if (j < 512)       v = g_ct[b * 512 + j];
        else if (j < 768)  v = g_h[b * 256 + (j - 512)];
        else if (j < 1024) v = g_c[b * 256 + (j - 768)];
        else               v = g_x[b * 128 + (j - 1024)];
        s += v * pgW[j];
    }
    __shared__ float red[128];
    red[tid] = s;
    __syncthreads();
    for (int off = 64; off; off >>= 1) {
        if (tid < off) red[tid] += red[tid + off];
        __syncthreads();
    }
    if (tid == 0) {
        float p = sigmoidf_(red[0] + pgb[0]);
        g_pgen[b] = p;
        if (outPG) outPG[b] = p;
    }
}

// ---------------- final distribution ----------------
__global__ void zeroZ_k() {
    int i = threadIdx.x;
    if (i < 512) g_Z[i] = 0.f;
}

__global__ void scale_k(float* __restrict__ out) {
    int i = blockIdx.x * 256 + threadIdx.x;
    if (i >= 512 * 12600) return;
    int b = i / 12600, r4 = i - b * 12600;
    float4* o = (float4*)out + (size_t)b * 12600 + r4;
    if (r4 < 12500) {
        float s = g_pgen[b] / g_Z[b];
        float4 v = *o;
        v.x *= s; v.y *= s; v.z *= s; v.w *= s;
        *o = v;
    } else {
        *o = make_float4(0.f, 0.f, 0.f, 0.f);
    }
}

__global__ void scatter_k(const int* __restrict__ ebev, float* __restrict__ out) {
    int idx = blockIdx.x * 256 + threadIdx.x;
    if (idx >= 512 * 512) return;
    int b = idx >> 9;
    float val = (1.f - g_pgen[b]) * g_ct[idx];
    atomicAdd(out + (size_t)b * EXTV_ + ebev[idx], val);
}

__global__ void copy_k(const float* __restrict__ src, float* __restrict__ dst, int n) {
    int i = blockIdx.x * 256 + threadIdx.x;
    if (i < n) dst[i] = src[i];
}

// ---------------- host-side symbol address helper ----------------
template <typename T>
static void* symaddr_(const T& sym) {
    void* p = nullptr;
    cudaGetSymbolAddress(&p, sym);
    return p;
}

// ---------------- host launcher ----------------
extern "C" void kernel_launch(void* const* d_in, const int* in_sizes, int n_in,
                              void* d_out, int out_size) {
    const int*   y    = (const int*)  d_in[0];
    const float* h0   = (const float*)d_in[1];
    const float* c0   = (const float*)d_in[2];
    const float* enc  = (const float*)d_in[3];
    const float* ct1  = (const float*)d_in[6];
    const int*   ebev = (const int*)  d_in[8];
    const float* cov  = (const float*)d_in[9];

    int wb = 10;
    for (int i = 10; i < n_in; i++) {
        if (in_sizes[i] == 6400000) { wb = i; break; }
    }
    const float* embW = (const float*)d_in[wb + 0];
    const float* xcW  = (const float*)d_in[wb + 1];
    const float* xcb  = (const float*)d_in[wb + 2];
    const float* Wih  = (const float*)d_in[wb + 3];
    const float* Whh  = (const float*)d_in[wb + 4];
    const float* bih  = (const float*)d_in[wb + 5];
    const float* bhh  = (const float*)d_in[wb + 6];
    const float* Wq   = (const float*)d_in[wb + 7];
    const float* Wk   = (const float*)d_in[wb + 8];
    const float* Wv   = (const float*)d_in[wb + 9];
    const float* Wo   = (const float*)d_in[wb + 10];
    const float* pgW  = (const float*)d_in[wb + 11];
    const float* pgb  = (const float*)d_in[wb + 12];
    const float* o1W  = (const float*)d_in[wb + 13];
    const float* o1b  = (const float*)d_in[wb + 14];
    const float* o2W  = (const float*)d_in[wb + 15];
    const float* o2b  = (const float*)d_in[wb + 16];
    float* out = (float*)d_out;
    const bool full = (out_size >= OUT_FULL);

    float* p_qk   = (float*)symaddr_(g_qk);
    __nv_bfloat16* p_A3 = (__nv_bfloat16*)symaddr_(g_A3);
    __nv_bfloat16* p_B3 = (__nv_bfloat16*)symaddr_(g_B3);
    float* p_wgT  = (float*)symaddr_(g_wgT);
    float* p_xcWT = (float*)symaddr_(g_xcWT);
    float* p_o1WT = (float*)symaddr_(g_o1WT);
    float* p_wvT  = (float*)symaddr_(g_wvT);
    float* p_woT  = (float*)symaddr_(g_woT);
    float* p_o2WT = (float*)symaddr_(g_o2WT);
    float* p_cat1 = (float*)symaddr_(g_cat1);
    float* p_x    = (float*)symaddr_(g_x);
    float* p_cat2 = (float*)symaddr_(g_cat2);
    float* p_gates= (float*)symaddr_(g_gates);
    float* p_pool = (float*)symaddr_(g_pooled);
    float* p_ct   = (float*)symaddr_(g_ct);
    float* p_cat3 = (float*)symaddr_(g_cat3);
    float* p_out1 = (float*)symaddr_(g_out1);

    cudaFuncSetAttribute(attn_pool2_k, cudaFuncAttributeMaxDynamicSharedMemorySize, ATTN_SMEM);
    cudaFuncSetAttribute(qk_mma_k, cudaFuncAttributeMaxDynamicSharedMemorySize, QK_SMEM);

    // launches 1-3, then qk_mma_k at slot 4 (the launch ncu profiles)
    buildA3_k<<<131072, 256>>>(enc, p_A3);
    buildB3_k<<<2048, 256>>>(Wq, Wk, p_B3);
    build_wgT_k<<<1536, 256>>>(Wih, Whh);
    qk_mma_k<<<dim3(8, 512), 256, QK_SMEM>>>(p_A3, p_B3, p_qk);
    attn_pool2_k<<<dim3(8, 512), 256, ATTN_SMEM>>>(p_qk, enc);

    // weight reshapes/transposes
    transpose_k<<<dim3(20, 4),   dim3(32, 8)>>>(xcW, p_xcWT, 128, 640);
    transpose_k<<<dim3(24, 8),   dim3(32, 8)>>>(o1W, p_o1WT, 256, 768);
    transpose_k<<<dim3(16, 16),  dim3(32, 8)>>>(Wv, p_wvT, 512, 512);
    transpose_k<<<dim3(16, 16),  dim3(32, 8)>>>(Wo, p_woT, 512, 512);
    transpose_k<<<dim3(8, 1563), dim3(32, 8)>>>(o2W, p_o2WT, 50000, 256);

    // embedding + x projection
    cat1_k<<<1280, 256>>>(ct1, embW, y);
    dense8_k<<<dim3(1, 64), 256>>>(p_cat1, p_xcWT, xcb, nullptr, p_x, 640, 128);

    // LSTM
    cat2_k<<<768, 256>>>(h0);
    dense8_k<<<dim3(4, 64), 256>>>(p_cat2, p_wgT, bih, bhh, p_gates, 384, 1024);
    lstm_k<<<512, 256>>>(c0, full ? out + OFF_H : nullptr, full ? out + OFF_C : nullptr);

    // attention tail: per-head Wv fold + Wo
    wv_head_k<<<dim3(4, 64), 128>>>();
    dense8_k<<<dim3(2, 64), 256>>>(p_pool, p_woT, nullptr, nullptr, p_ct, 512, 512);

    // pointer gate
    pgen_k<<<512, 128>>>(pgW, pgb, full ? out + OFF_PG : nullptr);

    // vocab head
    cat3_k<<<1536, 256>>>();
    dense8_k<<<dim3(1, 64), 256>>>(p_cat3, p_o1WT, o1b, nullptr, p_out1, 768, 256);
    zeroZ_k<<<1, 512>>>();
    sgemm_logits<<<dim3(391, 4), 256>>>(p_out1, p_o2WT, o2b, out, 50000, 256);

    // final distribution
    scale_k<<<25200, 256>>>(out);
    scatter_k<<<1024, 256>>>(ebev, out);

    if (full) {
        copy_k<<<1024, 256>>>(p_ct, out + OFF_CT1, 262144);
        copy_k<<<1024, 256>>>(p_ct, out + OFF_CT2, 262144);
        copy_k<<<256, 256>>>(cov, out + OFF_COV, 65536);
    }
}

// round 11
// speedup vs baseline: 1.3602x; 1.3602x over previous
#include <cuda_runtime.h>
#include <cuda_bf16.h>
#include <math.h>
#include <stdint.h>

// ---------------- problem constants ----------------
#define VV_  50000
#define EXTV_ 50400

// output offsets (flattened tuple order)
#define OFF_FD  0
#define OFF_H   25804800
#define OFF_C   25935872
#define OFF_CT1 26066944
#define OFF_CT2 26329088
#define OFF_PG  26591232
#define OFF_COV 26591744
#define OUT_FULL 26657280

// ---------------- device scratch (no cudaMalloc allowed) ----------------
__device__ float g_qk[65536 * 1024];            // Q | K per enc position (fp32)
__device__ __nv_bfloat16 g_A3[(size_t)65536 * 1536];  // [ah | ah | al] concat, K'=1536
__device__ __nv_bfloat16 g_B3[1024 * 1536];           // [bh | bl | bh] concat (K half pre-scaled by 1/8)
__device__ float g_wgT[384 * 1024];
__device__ float g_xcWT[640 * 128];
__device__ float g_o1WT[768 * 256];
__device__ float g_wvT[512 * 512];
__device__ float g_woT[512 * 512];
__device__ float g_o2WT[256 * 50000];
__device__ float g_cat1[512 * 640];
__device__ float g_x[512 * 128];
__device__ float g_cat2[512 * 384];
__device__ float g_gates[512 * 1024];
__device__ float g_h[512 * 256];
__device__ float g_c[512 * 256];
__device__ float g_e[512 * 8 * 512];
__device__ float g_pooled[512 * 512];
__device__ float g_ct[512 * 512];
__device__ float g_cat3[512 * 768];
__device__ float g_out1[512 * 256];
__device__ float g_pgen[512];
__device__ float g_Z[512];

__device__ __forceinline__ float sigmoidf_(float x) { return 1.0f / (1.0f + __expf(-x)); }

__device__ __forceinline__ uint32_t smem_u32_(const void* p) {
    uint32_t a;
    asm("{ .reg .u64 t; cvta.to.shared.u64 t, %1; cvt.u32.u64 %0, t; }" : "=r"(a) : "l"(p));
    return a;
}

__device__ __forceinline__ void cp_async16_(uint32_t dst, const void* src) {
    asm volatile("cp.async.cg.shared.global [%0], [%1], 16;" :: "r"(dst), "l"(src));
}

// ---------------- split-3 concat prep ----------------
__global__ void buildA3_k(const float* __restrict__ enc, __nv_bfloat16* __restrict__ A) {
    int i = blockIdx.x * 256 + threadIdx.x;
    if (i >= 65536 * 512) return;
    int r = i >> 9, k = i & 511;
    float v = enc[i];
    __nv_bfloat16 h = __float2bfloat16(v);
    __nv_bfloat16 lo = __float2bfloat16(v - __bfloat162float(h));
    size_t base = (size_t)r * 1536;
    A[base + k] = h;
    A[base + 512 + k] = h;
    A[base + 1024 + k] = lo;
}

// K rows (n >= 512) pre-scaled by 0.125 so attention skips the softmax scale
__global__ void buildB3_k(const float* __restrict__ Wq, const float* __restrict__ Wk,
                          __nv_bfloat16* __restrict__ B) {
    int i = blockIdx.x * 256 + threadIdx.x;
    if (i >= 1024 * 512) return;
    int n = i >> 9, k = i & 511;
    float v = (n < 512) ? Wq[(size_t)n * 512 + k]
                        : Wk[(size_t)(n - 512) * 512 + k] * 0.125f;
    __nv_bfloat16 h = __float2bfloat16(v);
    __nv_bfloat16 lo = __float2bfloat16(v - __bfloat162float(h));
    size_t base = (size_t)n * 1536;
    B[base + k] = h;
    B[base + 512 + k] = lo;
    B[base + 1024 + k] = h;
}

// ---------------- bf16 HMMA GEMM, 2-stage cp.async, low-reg variant ----------------
// C[65536,1024] = A'[.,1536] @ B'[.,1536]^T
// block tile 128(M)x64(N); 8 warps as 2(M)x4(N); warp tile 64x16 -> acc 32 regs
// smem: sA [2][128][72], sB [2][64][72] bf16 = 55296 B -> 2 CTAs/SM naturally
#define QK_SMEM ((2 * 128 * 72 + 2 * 64 * 72) * 2)
__global__ __launch_bounds__(256) void qk_mma_k(const __nv_bfloat16* __restrict__ A,
                                                const __nv_bfloat16* __restrict__ B,
                                                float* __restrict__ C) {
    extern __shared__ __nv_bfloat16 smem_bf[];
    // sA stages at 0 / 9216, sB stages at 18432 / 23040 (elem offsets)
    const int tid = threadIdx.x;
    const int wid = tid >> 5, lane = tid & 31;
    const int wm = (wid & 1) << 6;      // 0 / 64
    const int wn = (wid >> 1) << 4;     // 0 / 16 / 32 / 48
    const int m0 = blockIdx.y << 7;
    const int n0 = blockIdx.x << 6;
    const int lr = lane & 7;
    const int lg = lane >> 3;

    const int rA = tid >> 3;            // 0..31 (+32 per i)
    const int c8 = (tid & 7) << 3;

    float acc[4][2][4];
#pragma unroll
    for (int mi = 0; mi < 4; mi++)
#pragma unroll
        for (int ni = 0; ni < 2; ni++)
#pragma unroll
            for (int r = 0; r < 4; r++) acc[mi][ni][r] = 0.f;

    // prologue: stage tile 0 into stage 0
#pragma unroll
    for (int i = 0; i < 4; i++) {
        int r = rA + (i << 5);
        cp_async16_(smem_u32_(&smem_bf[r * 72 + c8]),
                    A + (size_t)(m0 + r) * 1536 + c8);
    }
#pragma unroll
    for (int i = 0; i < 2; i++) {
        int r = rA + (i << 5);
        if (r < 64)
            cp_async16_(smem_u32_(&smem_bf[18432 + r * 72 + c8]),
                        B + (size_t)(n0 + r) * 1536 + c8);
    }
    // note: rA in 0..31, i<2 covers rows 0..63 exactly
    asm volatile("cp.async.commit_group;" ::: "memory");

    for (int kt = 0; kt < 24; kt++) {
        const int buf = kt & 1;
        if (kt < 23) {
            const int nb = (kt + 1) & 1;
            const int kof = (kt + 1) << 6;
#pragma unroll
            for (int i = 0; i < 4; i++) {
                int r = rA + (i << 5);
                cp_async16_(smem_u32_(&smem_bf[nb * 9216 + r * 72 + c8]),
                            A + (size_t)(m0 + r) * 1536 + kof + c8);
            }
#pragma unroll
            for (int i = 0; i < 2; i++) {
                int r = rA + (i << 5);
                cp_async16_(smem_u32_(&smem_bf[18432 + nb * 4608 + r * 72 + c8]),
                            B + (size_t)(n0 + r) * 1536 + kof + c8);
            }
            asm volatile("cp.async.commit_group;" ::: "memory");
            asm volatile("cp.async.wait_group 1;" ::: "memory");
        } else {
            asm volatile("cp.async.wait_group 0;" ::: "memory");
        }
        __syncthreads();

        const __nv_bfloat16* bufA = smem_bf + buf * 9216;
        const __nv_bfloat16* bufB = smem_bf + 18432 + buf * 4608;
#pragma unroll
        for (int ks = 0; ks < 4; ks++) {
            uint32_t af[4][4];
#pragma unroll
            for (int mi = 0; mi < 4; mi++) {
                uint32_t addr = smem_u32_(
                    bufA + (wm + (mi << 4) + lr + ((lg & 1) << 3)) * 72 + (ks << 4) + ((lg >> 1) << 3));
                asm volatile("ldmatrix.sync.aligned.m8n8.x4.shared.b16 {%0,%1,%2,%3}, [%4];"
                             : "=r"(af[mi][0]), "=r"(af[mi][1]), "=r"(af[mi][2]), "=r"(af[mi][3])
                             : "r"(addr));
            }
            uint32_t bfr[2][2];
#pragma unroll
            for (int ni = 0; ni < 2; ni++) {
                uint32_t addr = smem_u32_(
                    bufB + (wn + (ni << 3) + lr) * 72 + (ks << 4) + ((lg & 1) << 3));
                asm volatile("ldmatrix.sync.aligned.m8n8.x2.shared.b16 {%0,%1}, [%2];"
                             : "=r"(bfr[ni][0]), "=r"(bfr[ni][1])
                             : "r"(addr));
            }
#pragma unroll
            for (int mi = 0; mi < 4; mi++)
#pragma unroll
                for (int ni = 0; ni < 2; ni++) {
                    asm volatile(
                        "mma.sync.aligned.m16n8k16.row.col.f32.bf16.bf16.f32 "
                        "{%0,%1,%2,%3}, {%4,%5,%6,%7}, {%8,%9}, {%0,%1,%2,%3};"
                        : "+f"(acc[mi][ni][0]), "+f"(acc[mi][ni][1]),
                          "+f"(acc[mi][ni][2]), "+f"(acc[mi][ni][3])
                        : "r"(af[mi][0]), "r"(af[mi][1]), "r"(af[mi][2]), "r"(af[mi][3]),
                          "r"(bfr[ni][0]), "r"(bfr[ni][1]));
                }
        }
        __syncthreads();
    }

    const int er = lane >> 2;
    const int ec = (lane & 3) << 1;
#pragma unroll
    for (int mi = 0; mi < 4; mi++) {
#pragma unroll
        for (int ni = 0; ni < 2; ni++) {
            size_t row = (size_t)(m0 + wm + (mi << 4) + er);
            int col = n0 + wn + (ni << 3) + ec;
            *(float2*)&C[row * 1024 + col] = make_float2(acc[mi][ni][0], acc[mi][ni][1]);
            *(float2*)&C[(row + 8) * 1024 + col] = make_float2(acc[mi][ni][2], acc[mi][ni][3]);
        }
    }
}

// ---------------- single-pass register-tiled pooled attention ----------------
#define ATTN_SMEM ((128 * 65 + 64 * 128 + 16 * 128 + 128) * 4)
__global__ __launch_bounds__(256) void attn_pool2_k(const float* __restrict__ qk,
                                                    const float* __restrict__ enc) {
    extern __shared__ float sm[];
    float* Qh   = sm;
    float* KhT  = Qh + 128 * 65;
    float* part = KhT + 64 * 128;
    float* w    = part + 16 * 128;
    const int h = blockIdx.x, b = blockIdx.y;
    const int tid = threadIdx.x;
    const int tx = tid & 15, ty = tid >> 4;

    for (int i = tid; i < 2048; i += 256) {
        int r = i >> 4, c4 = (i & 15) << 2;
        float4 v = *(const float4*)(qk + ((size_t)(b * 128 + r)) * 1024 + h * 64 + c4);
        float* dst = Qh + r * 65 + c4;
        dst[0] = v.x; dst[1] = v.y; dst[2] = v.z; dst[3] = v.w;
        float4 u = *(const float4*)(qk + ((size_t)(b * 128 + r)) * 1024 + 512 + h * 64 + c4);
        KhT[(c4 + 0) * 128 + r] = u.x;
        KhT[(c4 + 1) * 128 + r] = u.y;
        KhT[(c4 + 2) * 128 + r] = u.z;
        KhT[(c4 + 3) * 128 + r] = u.w;
    }
    __syncthreads();

    float acc[8][8];
#pragma unroll
    for (int i = 0; i < 8; i++)
#pragma unroll
        for (int j = 0; j < 8; j++) acc[i][j] = 0.f;

    for (int k = 0; k < 64; k++) {
        float a[8], bb[8];
#pragma unroll
        for (int i = 0; i < 8; i++) a[i] = Qh[(ty + (i << 4)) * 65 + k];
#pragma unroll
        for (int j = 0; j < 8; j++) bb[j] = KhT[k * 128 + tx + (j << 4)];
#pragma unroll
        for (int i = 0; i < 8; i++)
#pragma unroll
            for (int j = 0; j < 8; j++) acc[i][j] = fmaf(a[i], bb[j], acc[i][j]);
    }

    // K was pre-scaled by 1/8 in buildB3 -> scores already scaled
    float rs[8];
#pragma unroll
    for (int i = 0; i < 8; i++) {
        float s = 0.f;
#pragma unroll
        for (int j = 0; j < 8; j++) {
            float e = __expf(acc[i][j]);
            acc[i][j] = e;
            s += e;
        }
        rs[i] = s;
    }
#pragma unroll
    for (int m = 1; m < 16; m <<= 1)
#pragma unroll
        for (int i = 0; i < 8; i++) rs[i] += __shfl_xor_sync(0xffffffffu, rs[i], m);

    float cs[8];
#pragma unroll
    for (int j = 0; j < 8; j++) cs[j] = 0.f;
#pragma unroll
    for (int i = 0; i < 8; i++) {
        float zi = 1.f / rs[i];
#pragma unroll
        for (int j = 0; j < 8; j++) cs[j] = fmaf(acc[i][j], zi, cs[j]);
    }
#pragma unroll
    for (int j = 0; j < 8; j++) part[ty * 128 + tx + (j << 4)] = cs[j];
    __syncthreads();

    if (tid < 128) {
        float s = 0.f;
#pragma unroll
        for (int t2 = 0; t2 < 16; t2++) s += part[t2 * 128 + tid];
        w[tid] = s * (1.f / 128.f);
    }
    __syncthreads();

    float ea0 = 0.f, ea1 = 0.f;
    const float* encb = enc + (size_t)b * 128 * 512;
    for (int t = 0; t < 128; t++) {
        float wt = w[t];
        ea0 = fmaf(wt, encb[t * 512 + tid], ea0);
        ea1 = fmaf(wt, encb[t * 512 + tid + 256], ea1);
    }
    float* eo = g_e + ((size_t)b * 8 + h) * 512;
    eo[tid] = ea0;
    eo[tid + 256] = ea1;
}

// ---------------- weight prep kernels ----------------
__global__ void build_wgT_k(const float* __restrict__ Wih, const float* __restrict__ Whh) {
    int idx = blockIdx.x * 256 + threadIdx.x;
    if (idx >= 384 * 1024) return;
    int j = idx >> 10, r = idx & 1023;
    g_wgT[idx] = (j < 128) ? Wih[(size_t)r * 128 + j] : Whh[(size_t)r * 256 + (j - 128)];
}

__global__ void transpose_k(const float* __restrict__ in, float* __restrict__ out, int R, int C) {
    __shared__ float t[32][33];
    int c0 = blockIdx.x << 5, r0 = blockIdx.y << 5;
    int c = c0 + threadIdx.x;
    for (int i = threadIdx.y; i < 32; i += 8) {
        int r = r0 + i;
        if (r < R && c < C) t[i][threadIdx.x] = in[(size_t)r * C + c];
    }
    __syncthreads();
    int rr = r0 + threadIdx.x;
    for (int i = threadIdx.y; i < 32; i += 8) {
        int cc = c0 + i;
        if (cc < C && rr < R) out[(size_t)cc * R + rr] = t[threadIdx.x][i];
    }
}

// ---------------- concat builders ----------------
__global__ void cat1_k(const float* __restrict__ ct1, const float* __restrict__ embW,
                       const int* __restrict__ y) {
    int idx = blockIdx.x * 256 + threadIdx.x;
    if (idx >= 512 * 640) return;
    int b = idx / 640, j = idx - b * 640;
    g_cat1[idx] = (j < 512) ? ct1[(size_t)b * 512 + j]
                            : embW[(size_t)y[b] * 128 + (j - 512)];
}

__global__ void cat2_k(const float* __restrict__ h0) {
    int idx = blockIdx.x * 256 + threadIdx.x;
    if (idx >= 512 * 384) return;
    int b = idx / 384, j = idx - b * 384;
    g_cat2[idx] = (j < 128) ? g_x[b * 128 + j] : h0[(size_t)b * 256 + (j - 128)];
}

__global__ void cat3_k() {
    int idx = blockIdx.x * 256 + threadIdx.x;
    if (idx >= 512 * 768) return;
    int b = idx / 768, j = idx - b * 768;
    g_cat3[idx] = (j < 256) ? g_h[b * 256 + j] : g_ct[b * 512 + (j - 256)];
}

// ---------------- small dense ----------------
__global__ __launch_bounds__(256) void dense8_k(const float* __restrict__ X,
                                                const float* __restrict__ Wt,
                                                const float* __restrict__ b1,
                                                const float* __restrict__ b2,
                                                float* __restrict__ Y, int K, int N) {
    __shared__ float xs[8 * 768];
    const int tid = threadIdx.x;
    const int m0 = blockIdx.y << 3;
    const int col = (blockIdx.x << 8) + tid;
    for (int i = tid; i < (K << 3); i += 256) {
        int r = i / K, j = i - r * K;
        xs[i] = X[(size_t)(m0 + r) * K + j];
    }
    __syncthreads();
    if (col >= N) return;
    float acc[8];
#pragma unroll
    for (int r = 0; r < 8; r++) acc[r] = 0.f;
#pragma unroll 4
    for (int j = 0; j < K; j++) {
        float w = Wt[(size_t)j * N + col];
#pragma unroll
        for (int r = 0; r < 8; r++) acc[r] = fmaf(xs[r * K + j], w, acc[r]);
    }
    float bb = (b1 ? b1[col] : 0.f) + (b2 ? b2[col] : 0.f);
#pragma unroll
    for (int r = 0; r < 8; r++) Y[(size_t)(m0 + r) * N + col] = acc[r] + bb;
}

// ---------------- LSTM pointwise ----------------
__global__ void lstm_k(const float* __restrict__ c0, float* __restrict__ outH, float* __restrict__ outC) {
    int i = blockIdx.x * 256 + threadIdx.x;
    if (i >= 512 * 256) return;
    int b = i >> 8, u = i & 255;
    const float* g = &g_gates[b * 1024];
    float ig = sigmoidf_(g[u]);
    float fg = sigmoidf_(g[256 + u]);
    float gg = tanhf(g[512 + u]);
    float og = sigmoidf_(g[768 + u]);
    float cn = fg * c0[i] + ig * gg;
    float hn = og * tanhf(cn);
    g_h[i] = hn;
    g_c[i] = cn;
    if (outH) outH[i] = hn;
    if (outC) outC[i] = cn;
}

// ---------------- logits SGEMM fused with exp + row-sum ----------------
__global__ __launch_bounds__(256) void sgemm_logits(const float* __restrict__ A, const float* __restrict__ Bm,
                                                    const float* __restrict__ bias,
                                                    float* __restrict__ outE, int N, int K) {
    __shared__ float As[16][128];
    __shared__ float Bs[16][128];
    const int tid = threadIdx.x;
    const int tx = tid & 15, ty = tid >> 4;
    const int bm = blockIdx.y << 7, bn = blockIdx.x << 7;
    float acc[8][8];
#pragma unroll
    for (int i = 0; i < 8; i++)
#pragma unroll
        for (int j = 0; j < 8; j++) acc[i][j] = 0.f;

    for (int k0 = 0; k0 < K; k0 += 16) {
#pragma unroll
        for (int uu = 0; uu < 2; uu++) {
            int u = tid + (uu << 8);
            int r = u >> 2, kq = u & 3;
            float4 v = *reinterpret_cast<const float4*>(A + (size_t)(bm + r) * K + k0 + (kq << 2));
            As[(kq << 2) + 0][r] = v.x;
            As[(kq << 2) + 1][r] = v.y;
            As[(kq << 2) + 2][r] = v.z;
            As[(kq << 2) + 3][r] = v.w;
        }
#pragma unroll
        for (int uu = 0; uu < 2; uu++) {
            int u = tid + (uu << 8);
            int kr = u >> 5, nq = u & 31;
            int colb = bn + (nq << 2);
            const float* src = Bm + (size_t)(k0 + kr) * N;
            float4 v;
            if (colb + 3 < N) {
                v = *reinterpret_cast<const float4*>(src + colb);
            } else {
                v.x = (colb + 0 < N) ? src[colb + 0] : 0.f;
                v.y = (colb + 1 < N) ? src[colb + 1] : 0.f;
                v.z = (colb + 2 < N) ? src[colb + 2] : 0.f;
                v.w = (colb + 3 < N) ? src[colb + 3] : 0.f;
            }
            *reinterpret_cast<float4*>(&Bs[kr][nq << 2]) = v;
        }
        __syncthreads();
#pragma unroll
        for (int kk = 0; kk < 16; kk++) {
            float a[8], bv[8];
            *(float4*)&a[0] = *(const float4*)&As[kk][ty << 3];
            *(float4*)&a[4] = *(const float4*)&As[kk][(ty << 3) + 4];
            *(float4*)&bv[0] = *(const float4*)&Bs[kk][tx << 3];
            *(float4*)&bv[4] = *(const float4*)&Bs[kk][(tx << 3) + 4];
#pragma unroll
            for (int i = 0; i < 8; i++)
#pragma unroll
                for (int j = 0; j < 8; j++) acc[i][j] = fmaf(a[i], bv[j], acc[i][j]);
        }
        __syncthreads();
    }
#pragma unroll
    for (int i = 0; i < 8; i++) {
        int row = bm + (ty << 3) + i;
        float rs = 0.f;
        float* orow = outE + (size_t)row * EXTV_;
#pragma unroll
        for (int j = 0; j < 8; j++) {
            int col = bn + (tx << 3) + j;
            if (col < N) {
                float e = __expf(acc[i][j] + bias[col]);
                orow[col] = e;
                rs += e;
            }
        }
#pragma unroll
        for (int m = 1; m < 16; m <<= 1) rs += __shfl_xor_sync(0xffffffffu, rs, m);
        if (tx == 0) atomicAdd(&g_Z[row], rs);
    }
}

// ---------------- per-head Wv fold ----------------
__global__ __launch_bounds__(128) void wv_head_k() {
    __shared__ float es[8 * 2 * 512];
    const int tid = threadIdx.x;
    const int cx = blockIdx.x;
    const int b0 = blockIdx.y << 3;
    const int hbase = cx << 1;

    for (int i = tid; i < 8 * 2 * 512; i += 128) {
        int bb = i >> 10;
        int rem = i & 1023;
        int hh = rem >> 9;
        int j = rem & 511;
        es[i] = g_e[((size_t)(b0 + bb) * 8 + hbase + hh) * 512 + j];
    }
    __syncthreads();

    const int col = (cx << 7) + tid;
    const int hh = tid >> 6;
    float acc[8];
#pragma unroll
    for (int bb = 0; bb < 8; bb++) acc[bb] = 0.f;
    for (int j = 0; j < 512; j++) {
        float w0 = g_wvT[(size_t)j * 512 + col];
#pragma unroll
        for (int bb = 0; bb < 8; bb++)
            acc[bb] = fmaf(es[(bb << 10) + (hh << 9) + j], w0, acc[bb]);
    }
#pragma unroll
    for (int bb = 0; bb < 8; bb++)
        g_pooled[(size_t)(b0 + bb) * 512 + col] = acc[bb];
}

// ---------------- pointer gate ----------------
__global__ void pgen_k(const float* __restrict__ pgW, const float* __restrict__ pgb,
                       float* __restrict__ outPG) {
    int b = blockIdx.x;
    int tid = threadIdx.x;
    float s = 0.f;
    for (int j = tid; j < 1152; j += 128) {
        float v;
        if (j < 512)       v = g_ct[b * 512 + j];
        else if (j < 768)  v = g_h[b * 256 + (j - 512)];
        else if (j < 1024) v = g_c[b * 256 + (j - 768)];
        else               v = g_x[b * 128 + (j - 1024)];
        s += v * pgW[j];
    }
    __shared__ float red[128];
    red[tid] = s;
    __syncthreads();
    for (int off = 64; off; off >>= 1) {
        if (tid < off) red[tid] += red[tid + off];
        __syncthreads();
    }
    if (tid == 0) {
        float p = sigmoidf_(red[0] + pgb[0]);
        g_pgen[b] = p;
        if (outPG) outPG[b] = p;
    }
}

// ---------------- final distribution ----------------
__global__ void zeroZ_k() {
    int i = threadIdx.x;
    if (i < 512) g_Z[i] = 0.f;
}

__global__ void scale_k(float* __restrict__ out) {
    int i = blockIdx.x * 256 + threadIdx.x;
    if (i >= 512 * 12600) return;
    int b = i / 12600, r4 = i - b * 12600;
    float4* o = (float4*)out + (size_t)b * 12600 + r4;
    if (r4 < 12500) {
        float s = g_pgen[b] / g_Z[b];
        float4 v = *o;
        v.x *= s; v.y *= s; v.z *= s; v.w *= s;
        *o = v;
    } else {
        *o = make_float4(0.f, 0.f, 0.f, 0.f);
    }
}

__global__ void scatter_k(const int* __restrict__ ebev, float* __restrict__ out) {
    int idx = blockIdx.x * 256 + threadIdx.x;
    if (idx >= 512 * 512) return;
    int b = idx >> 9;
    float val = (1.f - g_pgen[b]) * g_ct[idx];
    atomicAdd(out + (size_t)b * EXTV_ + ebev[idx], val);
}

__global__ void copy_k(const float* __restrict__ src, float* __restrict__ dst, int n) {
    int i = blockIdx.x * 256 + threadIdx.x;
    if (i < n) dst[i] = src[i];
}

// ---------------- host-side symbol address helper ----------------
template <typename T>
static void* symaddr_(const T& sym) {
    void* p = nullptr;
    cudaGetSymbolAddress(&p, sym);
    return p;
}

// ---------------- host launcher ----------------
extern "C" void kernel_launch(void* const* d_in, const int* in_sizes, int n_in,
                              void* d_out, int out_size) {
    const int*   y    = (const int*)  d_in[0];
    const float* h0   = (const float*)d_in[1];
    const float* c0   = (const float*)d_in[2];
    const float* enc  = (const float*)d_in[3];
    const float* ct1  = (const float*)d_in[6];
    const int*   ebev = (const int*)  d_in[8];
    const float* cov  = (const float*)d_in[9];

    int wb = 10;
    for (int i = 10; i < n_in; i++) {
        if (in_sizes[i] == 6400000) { wb = i; break; }
    }
    const float* embW = (const float*)d_in[wb + 0];
    const float* xcW  = (const float*)d_in[wb + 1];
    const float* xcb  = (const float*)d_in[wb + 2];
    const float* Wih  = (const float*)d_in[wb + 3];
    const float* Whh  = (const float*)d_in[wb + 4];
    const float* bih  = (const float*)d_in[wb + 5];
    const float* bhh  = (const float*)d_in[wb + 6];
    const float* Wq   = (const float*)d_in[wb + 7];
    const float* Wk   = (const float*)d_in[wb + 8];
    const float* Wv   = (const float*)d_in[wb + 9];
    const float* Wo   = (const float*)d_in[wb + 10];
    const float* pgW  = (const float*)d_in[wb + 11];
    const float* pgb  = (const float*)d_in[wb + 12];
    const float* o1W  = (const float*)d_in[wb + 13];
    const float* o1b  = (const float*)d_in[wb + 14];
    const float* o2W  = (const float*)d_in[wb + 15];
    const float* o2b  = (const float*)d_in[wb + 16];
    float* out = (float*)d_out;
    const bool full = (out_size >= OUT_FULL);

    float* p_qk   = (float*)symaddr_(g_qk);
    __nv_bfloat16* p_A3 = (__nv_bfloat16*)symaddr_(g_A3);
    __nv_bfloat16* p_B3 = (__nv_bfloat16*)symaddr_(g_B3);
    float* p_wgT  = (float*)symaddr_(g_wgT);
    float* p_xcWT = (float*)symaddr_(g_xcWT);
    float* p_o1WT = (float*)symaddr_(g_o1WT);
    float* p_wvT  = (float*)symaddr_(g_wvT);
    float* p_woT  = (float*)symaddr_(g_woT);
    float* p_o2WT = (float*)symaddr_(g_o2WT);
    float* p_cat1 = (float*)symaddr_(g_cat1);
    float* p_x    = (float*)symaddr_(g_x);
    float* p_cat2 = (float*)symaddr_(g_cat2);
    float* p_gates= (float*)symaddr_(g_gates);
    float* p_pool = (float*)symaddr_(g_pooled);
    float* p_ct   = (float*)symaddr_(g_ct);
    float* p_cat3 = (float*)symaddr_(g_cat3);
    float* p_out1 = (float*)symaddr_(g_out1);

    cudaFuncSetAttribute(attn_pool2_k, cudaFuncAttributeMaxDynamicSharedMemorySize, ATTN_SMEM);
    cudaFuncSetAttribute(qk_mma_k, cudaFuncAttributeMaxDynamicSharedMemorySize, QK_SMEM);

    // launches 1-3, then qk_mma_k at slot 4 (the launch ncu profiles)
    buildA3_k<<<131072, 256>>>(enc, p_A3);
    buildB3_k<<<2048, 256>>>(Wq, Wk, p_B3);
    build_wgT_k<<<1536, 256>>>(Wih, Whh);
    qk_mma_k<<<dim3(16, 512), 256, QK_SMEM>>>(p_A3, p_B3, p_qk);
    attn_pool2_k<<<dim3(8, 512), 256, ATTN_SMEM>>>(p_qk, enc);

    // weight reshapes/transposes
    transpose_k<<<dim3(20, 4),   dim3(32, 8)>>>(xcW, p_xcWT, 128, 640);
    transpose_k<<<dim3(24, 8),   dim3(32, 8)>>>(o1W, p_o1WT, 256, 768);
    transpose_k<<<dim3(16, 16),  dim3(32, 8)>>>(Wv, p_wvT, 512, 512);
    transpose_k<<<dim3(16, 16),  dim3(32, 8)>>>(Wo, p_woT, 512, 512);
    transpose_k<<<dim3(8, 1563), dim3(32, 8)>>>(o2W, p_o2WT, 50000, 256);

    // embedding + x projection
    cat1_k<<<1280, 256>>>(ct1, embW, y);
    dense8_k<<<dim3(1, 64), 256>>>(p_cat1, p_xcWT, xcb, nullptr, p_x, 640, 128);

    // LSTM
    cat2_k<<<768, 256>>>(h0);
    dense8_k<<<dim3(4, 64), 256>>>(p_cat2, p_wgT, bih, bhh, p_gates, 384, 1024);
    lstm_k<<<512, 256>>>(c0, full ? out + OFF_H : nullptr, full ? out + OFF_C : nullptr);

    // attention tail: per-head Wv fold + Wo
    wv_head_k<<<dim3(4, 64), 128>>>();
    dense8_k<<<dim3(2, 64), 256>>>(p_pool, p_woT, nullptr, nullptr, p_ct, 512, 512);

    // pointer gate
    pgen_k<<<512, 128>>>(pgW, pgb, full ? out + OFF_PG : nullptr);

    // vocab head
    cat3_k<<<1536, 256>>>();
    dense8_k<<<dim3(1, 64), 256>>>(p_cat3, p_o1WT, o1b, nullptr, p_out1, 768, 256);
    zeroZ_k<<<1, 512>>>();
    sgemm_logits<<<dim3(391, 4), 256>>>(p_out1, p_o2WT, o2b, out, 50000, 256);

    // final distribution
    scale_k<<<25200, 256>>>(out);
    scatter_k<<<1024, 256>>>(ebev, out);

    if (full) {
        copy_k<<<1024, 256>>>(p_ct, out + OFF_CT1, 262144);
        copy_k<<<1024, 256>>>(p_ct, out + OFF_CT2, 262144);
        copy_k<<<256, 256>>>(cov, out + OFF_COV, 65536);
    }
}

// round 12
// speedup vs baseline: 1.4584x; 1.0722x over previous
#include <cuda_runtime.h>
#include <cuda_bf16.h>
#include <math.h>
#include <stdint.h>

// ---------------- problem constants ----------------
#define VV_  50000
#define EXTV_ 50400

// output offsets (flattened tuple order)
#define OFF_FD  0
#define OFF_H   25804800
#define OFF_C   25935872
#define OFF_CT1 26066944
#define OFF_CT2 26329088
#define OFF_PG  26591232
#define OFF_COV 26591744
#define OUT_FULL 26657280

// ---------------- device scratch (no cudaMalloc allowed) ----------------
__device__ float g_qk[65536 * 1024];            // Q | K per enc position (fp32)
__device__ __nv_bfloat16 g_A3[(size_t)65536 * 1536];  // [ah | ah | al] concat, K'=1536
__device__ __nv_bfloat16 g_B3[1024 * 1536];           // [bh | bl | bh] (K half pre-scaled by 1/8)
__device__ float g_wgT[384 * 1024];
__device__ float g_xcWT[640 * 128];
__device__ float g_o1WT[768 * 256];
__device__ float g_wvT[512 * 512];
__device__ float g_woT[512 * 512];
__device__ float g_o2WT[256 * 50000];
__device__ float g_cat1[512 * 640];
__device__ float g_x[512 * 128];
__device__ float g_cat2[512 * 384];
__device__ float g_gates[512 * 1024];
__device__ float g_h[512 * 256];
__device__ float g_c[512 * 256];
__device__ float g_e[512 * 8 * 512];
__device__ float g_pooled[512 * 512];
__device__ float g_ct[512 * 512];
__device__ float g_cat3[512 * 768];
__device__ float g_out1[512 * 256];
__device__ float g_pgen[512];
__device__ float g_Z[512];

__device__ __forceinline__ float sigmoidf_(float x) { return 1.0f / (1.0f + __expf(-x)); }

__device__ __forceinline__ uint32_t smem_u32_(const void* p) {
    uint32_t a;
    asm("{ .reg .u64 t; cvta.to.shared.u64 t, %1; cvt.u32.u64 %0, t; }" : "=r"(a) : "l"(p));
    return a;
}

__device__ __forceinline__ void cp_async16_(uint32_t dst, const void* src) {
    asm volatile("cp.async.cg.shared.global [%0], [%1], 16;" :: "r"(dst), "l"(src));
}

// ---------------- split-3 concat prep ----------------
__global__ void buildA3_k(const float* __restrict__ enc, __nv_bfloat16* __restrict__ A) {
    int i = blockIdx.x * 256 + threadIdx.x;
    if (i >= 65536 * 512) return;
    int r = i >> 9, k = i & 511;
    float v = enc[i];
    __nv_bfloat16 h = __float2bfloat16(v);
    __nv_bfloat16 lo = __float2bfloat16(v - __bfloat162float(h));
    size_t base = (size_t)r * 1536;
    A[base + k] = h;
    A[base + 512 + k] = h;
    A[base + 1024 + k] = lo;
}

// K rows (n >= 512) pre-scaled by 0.125 so attention skips the softmax scale
__global__ void buildB3_k(const float* __restrict__ Wq, const float* __restrict__ Wk,
                          __nv_bfloat16* __restrict__ B) {
    int i = blockIdx.x * 256 + threadIdx.x;
    if (i >= 1024 * 512) return;
    int n = i >> 9, k = i & 511;
    float v = (n < 512) ? Wq[(size_t)n * 512 + k]
                        : Wk[(size_t)(n - 512) * 512 + k] * 0.125f;
    __nv_bfloat16 h = __float2bfloat16(v);
    __nv_bfloat16 lo = __float2bfloat16(v - __bfloat162float(h));
    size_t base = (size_t)n * 1536;
    B[base + k] = h;
    B[base + 512 + k] = lo;
    B[base + 1024 + k] = h;
}

// ---------------- bf16 HMMA GEMM, 2-stage cp.async, 4-warp / 64x32 warp tile ----------------
// C[65536,1024] = A'[.,1536] @ B'[.,1536]^T
// block tile 128(M)x64(N); 4 warps as 2(M)x2(N); warp tile 64x32 -> 1.5 matrix-loads/MMA
// smem: sA [2][128][72], sB [2][64][72] bf16 = 55296 B -> 4 CTAs/SM
#define QK_SMEM ((2 * 128 * 72 + 2 * 64 * 72) * 2)
__global__ __launch_bounds__(128) void qk_mma_k(const __nv_bfloat16* __restrict__ A,
                                                const __nv_bfloat16* __restrict__ B,
                                                float* __restrict__ C) {
    extern __shared__ __nv_bfloat16 smem_bf[];
    const int tid = threadIdx.x;          // 0..127
    const int wid = tid >> 5, lane = tid & 31;
    const int wm = (wid & 1) << 6;        // 0 / 64
    const int wn = (wid >> 1) << 5;       // 0 / 32
    const int m0 = blockIdx.y << 7;
    const int n0 = blockIdx.x << 6;
    const int lr = lane & 7;
    const int lg = lane >> 3;

    const int rA = tid >> 3;              // 0..15
    const int c8 = (tid & 7) << 3;

    float acc[4][4][4];
#pragma unroll
    for (int mi = 0; mi < 4; mi++)
#pragma unroll
        for (int ni = 0; ni < 4; ni++)
#pragma unroll
            for (int r = 0; r < 4; r++) acc[mi][ni][r] = 0.f;

    // prologue: stage tile 0 into stage 0
#pragma unroll
    for (int i = 0; i < 8; i++) {
        int r = rA + (i << 4);
        cp_async16_(smem_u32_(&smem_bf[r * 72 + c8]),
                    A + (size_t)(m0 + r) * 1536 + c8);
    }
#pragma unroll
    for (int i = 0; i < 4; i++) {
        int r = rA + (i << 4);
        cp_async16_(smem_u32_(&smem_bf[18432 + r * 72 + c8]),
                    B + (size_t)(n0 + r) * 1536 + c8);
    }
    asm volatile("cp.async.commit_group;" ::: "memory");

    for (int kt = 0; kt < 24; kt++) {
        const int buf = kt & 1;
        if (kt < 23) {
            const int nb = (kt + 1) & 1;
            const int kof = (kt + 1) << 6;
#pragma unroll
            for (int i = 0; i < 8; i++) {
                int r = rA + (i << 4);
                cp_async16_(smem_u32_(&smem_bf[nb * 9216 + r * 72 + c8]),
                            A + (size_t)(m0 + r) * 1536 + kof + c8);
            }
#pragma unroll
            for (int i = 0; i < 4; i++) {
                int r = rA + (i << 4);
                cp_async16_(smem_u32_(&smem_bf[18432 + nb * 4608 + r * 72 + c8]),
                            B + (size_t)(n0 + r) * 1536 + kof + c8);
            }
            asm volatile("cp.async.commit_group;" ::: "memory");
            asm volatile("cp.async.wait_group 1;" ::: "memory");
        } else {
            asm volatile("cp.async.wait_group 0;" ::: "memory");
        }
        __syncthreads();

        const __nv_bfloat16* bufA = smem_bf + buf * 9216;
        const __nv_bfloat16* bufB = smem_bf + 18432 + buf * 4608;
#pragma unroll
        for (int ks = 0; ks < 4; ks++) {
            uint32_t af[4][4];
#pragma unroll
            for (int mi = 0; mi < 4; mi++) {
                uint32_t addr = smem_u32_(
                    bufA + (wm + (mi << 4) + lr + ((lg & 1) << 3)) * 72 + (ks << 4) + ((lg >> 1) << 3));
                asm volatile("ldmatrix.sync.aligned.m8n8.x4.shared.b16 {%0,%1,%2,%3}, [%4];"
                             : "=r"(af[mi][0]), "=r"(af[mi][1]), "=r"(af[mi][2]), "=r"(af[mi][3])
                             : "r"(addr));
            }
            // B: two x4 loads cover all 32 N-cols (4 matrices each)
            uint32_t bq[2][4];
#pragma unroll
            for (int nf = 0; nf < 2; nf++) {
                uint32_t addr = smem_u32_(
                    bufB + (wn + (nf << 4) + ((lg >> 1) << 3) + lr) * 72 + (ks << 4) + ((lg & 1) << 3));
                asm volatile("ldmatrix.sync.aligned.m8n8.x4.shared.b16 {%0,%1,%2,%3}, [%4];"
                             : "=r"(bq[nf][0]), "=r"(bq[nf][1]), "=r"(bq[nf][2]), "=r"(bq[nf][3])
                             : "r"(addr));
            }
#pragma unroll
            for (int mi = 0; mi < 4; mi++)
#pragma unroll
                for (int ni = 0; ni < 4; ni++) {
                    const uint32_t b0 = bq[ni >> 1][(ni & 1) << 1];
                    const uint32_t b1 = bq[ni >> 1][((ni & 1) << 1) + 1];
                    asm volatile(
                        "mma.sync.aligned.m16n8k16.row.col.f32.bf16.bf16.f32 "
                        "{%0,%1,%2,%3}, {%4,%5,%6,%7}, {%8,%9}, {%0,%1,%2,%3};"
                        : "+f"(acc[mi][ni][0]), "+f"(acc[mi][ni][1]),
                          "+f"(acc[mi][ni][2]), "+f"(acc[mi][ni][3])
                        : "r"(af[mi][0]), "r"(af[mi][1]), "r"(af[mi][2]), "r"(af[mi][3]),
                          "r"(b0), "r"(b1));
                }
        }
        __syncthreads();
    }

    const int er = lane >> 2;
    const int ec = (lane & 3) << 1;
#pragma unroll
    for (int mi = 0; mi < 4; mi++) {
#pragma unroll
        for (int ni = 0; ni < 4; ni++) {
            size_t row = (size_t)(m0 + wm + (mi << 4) + er);
            int col = n0 + wn + (ni << 3) + ec;
            *(float2*)&C[row * 1024 + col] = make_float2(acc[mi][ni][0], acc[mi][ni][1]);
            *(float2*)&C[(row + 8) * 1024 + col] = make_float2(acc[mi][ni][2], acc[mi][ni][3]);
        }
    }
}

// ---------------- single-pass register-tiled pooled attention ----------------
#define ATTN_SMEM ((128 * 65 + 64 * 128 + 16 * 128 + 128) * 4)
__global__ __launch_bounds__(256) void attn_pool2_k(const float* __restrict__ qk,
                                                    const float* __restrict__ enc) {
    extern __shared__ float sm[];
    float* Qh   = sm;
    float* KhT  = Qh + 128 * 65;
    float* part = KhT + 64 * 128;
    float* w    = part + 16 * 128;
    const int h = blockIdx.x, b = blockIdx.y;
    const int tid = threadIdx.x;
    const int tx = tid & 15, ty = tid >> 4;

    for (int i = tid; i < 2048; i += 256) {
        int r = i >> 4, c4 = (i & 15) << 2;
        float4 v = *(const float4*)(qk + ((size_t)(b * 128 + r)) * 1024 + h * 64 + c4);
        float* dst = Qh + r * 65 + c4;
        dst[0] = v.x; dst[1] = v.y; dst[2] = v.z; dst[3] = v.w;
        float4 u = *(const float4*)(qk + ((size_t)(b * 128 + r)) * 1024 + 512 + h * 64 + c4);
        KhT[(c4 + 0) * 128 + r] = u.x;
        KhT[(c4 + 1) * 128 + r] = u.y;
        KhT[(c4 + 2) * 128 + r] = u.z;
        KhT[(c4 + 3) * 128 + r] = u.w;
    }
    __syncthreads();

    float acc[8][8];
#pragma unroll
    for (int i = 0; i < 8; i++)
#pragma unroll
        for (int j = 0; j < 8; j++) acc[i][j] = 0.f;

    for (int k = 0; k < 64; k++) {
        float a[8], bb[8];
#pragma unroll
        for (int i = 0; i < 8; i++) a[i] = Qh[(ty + (i << 4)) * 65 + k];
#pragma unroll
        for (int j = 0; j < 8; j++) bb[j] = KhT[k * 128 + tx + (j << 4)];
#pragma unroll
        for (int i = 0; i < 8; i++)
#pragma unroll
            for (int j = 0; j < 8; j++) acc[i][j] = fmaf(a[i], bb[j], acc[i][j]);
    }

    // K was pre-scaled by 1/8 in buildB3 -> scores already scaled
    float rs[8];
#pragma unroll
    for (int i = 0; i < 8; i++) {
        float s = 0.f;
#pragma unroll
        for (int j = 0; j < 8; j++) {
            float e = __expf(acc[i][j]);
            acc[i][j] = e;
            s += e;
        }
        rs[i] = s;
    }
#pragma unroll
    for (int m = 1; m < 16; m <<= 1)
#pragma unroll
        for (int i = 0; i < 8; i++) rs[i] += __shfl_xor_sync(0xffffffffu, rs[i], m);

    float cs[8];
#pragma unroll
    for (int j = 0; j < 8; j++) cs[j] = 0.f;
#pragma unroll
    for (int i = 0; i < 8; i++) {
        float zi = 1.f / rs[i];
#pragma unroll
        for (int j = 0; j < 8; j++) cs[j] = fmaf(acc[i][j], zi, cs[j]);
    }
#pragma unroll
    for (int j = 0; j < 8; j++) part[ty * 128 + tx + (j << 4)] = cs[j];
    __syncthreads();

    if (tid < 128) {
        float s = 0.f;
#pragma unroll
        for (int t2 = 0; t2 < 16; t2++) s += part[t2 * 128 + tid];
        w[tid] = s * (1.f / 128.f);
    }
    __syncthreads();

    float ea0 = 0.f, ea1 = 0.f;
    const float* encb = enc + (size_t)b * 128 * 512;
    for (int t = 0; t < 128; t++) {
        float wt = w[t];
        ea0 = fmaf(wt, encb[t * 512 + tid], ea0);
        ea1 = fmaf(wt, encb[t * 512 + tid + 256], ea1);
    }
    float* eo = g_e + ((size_t)b * 8 + h) * 512;
    eo[tid] = ea0;
    eo[tid + 256] = ea1;
}

// ---------------- weight prep kernels ----------------
__global__ void build_wgT_k(const float* __restrict__ Wih, const float* __restrict__ Whh) {
    int idx = blockIdx.x * 256 + threadIdx.x;
    if (idx >= 384 * 1024) return;
    int j = idx >> 10, r = idx & 1023;
    g_wgT[idx] = (j < 128) ? Wih[(size_t)r * 128 + j] : Whh[(size_t)r * 256 + (j - 128)];
}

__global__ void transpose_k(const float* __restrict__ in, float* __restrict__ out, int R, int C) {
    __shared__ float t[32][33];
    int c0 = blockIdx.x << 5, r0 = blockIdx.y << 5;
    int c = c0 + threadIdx.x;
    for (int i = threadIdx.y; i < 32; i += 8) {
        int r = r0 + i;
        if (r < R && c < C) t[i][threadIdx.x] = in[(size_t)r * C + c];
    }
    __syncthreads();
    int rr = r0 + threadIdx.x;
    for (int i = threadIdx.y; i < 32; i += 8) {
        int cc = c0 + i;
        if (cc < C && rr < R) out[(size_t)cc * R + rr] = t[threadIdx.x][i];
    }
}

// ---------------- concat builders ----------------
__global__ void cat1_k(const float* __restrict__ ct1, const float* __restrict__ embW,
                       const int* __restrict__ y) {
    int idx = blockIdx.x * 256 + threadIdx.x;
    if (idx >= 512 * 640) return;
    int b = idx / 640, j = idx - b * 640;
    g_cat1[idx] = (j < 512) ? ct1[(size_t)b * 512 + j]
                            : embW[(size_t)y[b] * 128 + (j - 512)];
}

__global__ void cat2_k(const float* __restrict__ h0) {
    int idx = blockIdx.x * 256 + threadIdx.x;
    if (idx >= 512 * 384) return;
    int b = idx / 384, j = idx - b * 384;
    g_cat2[idx] = (j < 128) ? g_x[b * 128 + j] : h0[(size_t)b * 256 + (j - 128)];
}

__global__ void cat3_k() {
    int idx = blockIdx.x * 256 + threadIdx.x;
    if (idx >= 512 * 768) return;
    int b = idx / 768, j = idx - b * 768;
    g_cat3[idx] = (j < 256) ? g_h[b * 256 + j] : g_ct[b * 512 + (j - 256)];
}

// ---------------- small dense ----------------
__global__ __launch_bounds__(256) void dense8_k(const float* __restrict__ X,
                                                const float* __restrict__ Wt,
                                                const float* __restrict__ b1,
                                                const float* __restrict__ b2,
                                                float* __restrict__ Y, int K, int N) {
    __shared__ float xs[8 * 768];
    const int tid = threadIdx.x;
    const int m0 = blockIdx.y << 3;
    const int col = (blockIdx.x << 8) + tid;
    for (int i = tid; i < (K << 3); i += 256) {
        int r = i / K, j = i - r * K;
        xs[i] = X[(size_t)(m0 + r) * K + j];
    }
    __syncthreads();
    if (col >= N) return;
    float acc[8];
#pragma unroll
    for (int r = 0; r < 8; r++) acc[r] = 0.f;
#pragma unroll 4
    for (int j = 0; j < K; j++) {
        float w = Wt[(size_t)j * N + col];
#pragma unroll
        for (int r = 0; r < 8; r++) acc[r] = fmaf(xs[r * K + j], w, acc[r]);
    }
    float bb = (b1 ? b1[col] : 0.f) + (b2 ? b2[col] : 0.f);
#pragma unroll
    for (int r = 0; r < 8; r++) Y[(size_t)(m0 + r) * N + col] = acc[r] + bb;
}

// ---------------- LSTM pointwise ----------------
__global__ void lstm_k(const float* __restrict__ c0, float* __restrict__ outH, float* __restrict__ outC) {
    int i = blockIdx.x * 256 + threadIdx.x;
    if (i >= 512 * 256) return;
    int b = i >> 8, u = i & 255;
    const float* g = &g_gates[b * 1024];
    float ig = sigmoidf_(g[u]);
    float fg = sigmoidf_(g[256 + u]);
    float gg = tanhf(g[512 + u]);
    float og = sigmoidf_(g[768 + u]);
    float cn = fg * c0[i] + ig * gg;
    float hn = og * tanhf(cn);
    g_h[i] = hn;
    g_c[i] = cn;
    if (outH) outH[i] = hn;
    if (outC) outC[i] = cn;
}

// ---------------- logits SGEMM fused with exp + row-sum ----------------
__global__ __launch_bounds__(256) void sgemm_logits(const float* __restrict__ A, const float* __restrict__ Bm,
                                                    const float* __restrict__ bias,
                                                    float* __restrict__ outE, int N, int K) {
    __shared__ float As[16][128];
    __shared__ float Bs[16][128];
    const int tid = threadIdx.x;
    const int tx = tid & 15, ty = tid >> 4;
    const int bm = blockIdx.y << 7, bn = blockIdx.x << 7;
    float acc[8][8];
#pragma unroll
    for (int i = 0; i < 8; i++)
#pragma unroll
        for (int j = 0; j < 8; j++) acc[i][j] = 0.f;

    for (int k0 = 0; k0 < K; k0 += 16) {
#pragma unroll
        for (int uu = 0; uu < 2; uu++) {
            int u = tid + (uu << 8);
            int r = u >> 2, kq = u & 3;
            float4 v = *reinterpret_cast<const float4*>(A + (size_t)(bm + r) * K + k0 + (kq << 2));
            As[(kq << 2) + 0][r] = v.x;
            As[(kq << 2) + 1][r] = v.y;
            As[(kq << 2) + 2][r] = v.z;
            As[(kq << 2) + 3][r] = v.w;
        }
#pragma unroll
        for (int uu = 0; uu < 2; uu++) {
            int u = tid + (uu << 8);
            int kr = u >> 5, nq = u & 31;
            int colb = bn + (nq << 2);
            const float* src = Bm + (size_t)(k0 + kr) * N;
            float4 v;
            if (colb + 3 < N) {
                v = *reinterpret_cast<const float4*>(src + colb);
            } else {
                v.x = (colb + 0 < N) ? src[colb + 0] : 0.f;
                v.y = (colb + 1 < N) ? src[colb + 1] : 0.f;
                v.z = (colb + 2 < N) ? src[colb + 2] : 0.f;
                v.w = (colb + 3 < N) ? src[colb + 3] : 0.f;
            }
            *reinterpret_cast<float4*>(&Bs[kr][nq << 2]) = v;
        }
        __syncthreads();
#pragma unroll
        for (int kk = 0; kk < 16; kk++) {
            float a[8], bv[8];
            *(float4*)&a[0] = *(const float4*)&As[kk][ty << 3];
            *(float4*)&a[4] = *(const float4*)&As[kk][(ty << 3) + 4];
            *(float4*)&bv[0] = *(const float4*)&Bs[kk][tx << 3];
            *(float4*)&bv[4] = *(const float4*)&Bs[kk][(tx << 3) + 4];
#pragma unroll
            for (int i = 0; i < 8; i++)
#pragma unroll
                for (int j = 0; j < 8; j++) acc[i][j] = fmaf(a[i], bv[j], acc[i][j]);
        }
        __syncthreads();
    }
#pragma unroll
    for (int i = 0; i < 8; i++) {
        int row = bm + (ty << 3) + i;
        float rs = 0.f;
        float* orow = outE + (size_t)row * EXTV_;
#pragma unroll
        for (int j = 0; j < 8; j++) {
            int col = bn + (tx << 3) + j;
            if (col < N) {
                float e = __expf(acc[i][j] + bias[col]);
                orow[col] = e;
                rs += e;
            }
        }
#pragma unroll
        for (int m = 1; m < 16; m <<= 1) rs += __shfl_xor_sync(0xffffffffu, rs, m);
        if (tx == 0) atomicAdd(&g_Z[row], rs);
    }
}

// ---------------- per-head Wv fold ----------------
__global__ __launch_bounds__(128) void wv_head_k() {
    __shared__ float es[8 * 2 * 512];
    const int tid = threadIdx.x;
    const int cx = blockIdx.x;
    const int b0 = blockIdx.y << 3;
    const int hbase = cx << 1;

    for (int i = tid; i < 8 * 2 * 512; i += 128) {
        int bb = i >> 10;
        int rem = i & 1023;
        int hh = rem >> 9;
        int j = rem & 511;
        es[i] = g_e[((size_t)(b0 + bb) * 8 + hbase + hh) * 512 + j];
    }
    __syncthreads();

    const int col = (cx << 7) + tid;
    const int hh = tid >> 6;
    float acc[8];
#pragma unroll
    for (int bb = 0; bb < 8; bb++) acc[bb] = 0.f;
    for (int j = 0; j < 512; j++) {
        float w0 = g_wvT[(size_t)j * 512 + col];
#pragma unroll
        for (int bb = 0; bb < 8; bb++)
            acc[bb] = fmaf(es[(bb << 10) + (hh << 9) + j], w0, acc[bb]);
    }
#pragma unroll
    for (int bb = 0; bb < 8; bb++)
        g_pooled[(size_t)(b0 + bb) * 512 + col] = acc[bb];
}

// ---------------- pointer gate ----------------
__global__ void pgen_k(const float* __restrict__ pgW, const float* __restrict__ pgb,
                       float* __restrict__ outPG) {
    int b = blockIdx.x;
    int tid = threadIdx.x;
    float s = 0.f;
    for (int j = tid; j < 1152; j += 128) {
        float v;
        if (j < 512)       v = g_ct[b * 512 + j];
        else if (j < 768)  v = g_h[b * 256 + (j - 512)];
        else if (j < 1024) v = g_c[b * 256 + (j - 768)];
        else               v = g_x[b * 128 + (j - 1024)];
        s += v * pgW[j];
    }
    __shared__ float red[128];
    red[tid] = s;
    __syncthreads();
    for (int off = 64; off; off >>= 1) {
        if (tid < off) red[tid] += red[tid + off];
        __syncthreads();
    }
    if (tid == 0) {
        float p = sigmoidf_(red[0] + pgb[0]);
        g_pgen[b] = p;
        if (outPG) outPG[b] = p;
    }
}

// ---------------- final distribution ----------------
__global__ void zeroZ_k() {
    int i = threadIdx.x;
    if (i < 512) g_Z[i] = 0.f;
}

__global__ void scale_k(float* __restrict__ out) {
    int i = blockIdx.x * 256 + threadIdx.x;
    if (i >= 512 * 12600) return;
    int b = i / 12600, r4 = i - b * 12600;
    float4* o = (float4*)out + (size_t)b * 12600 + r4;
    if (r4 < 12500) {
        float s = g_pgen[b] / g_Z[b];
        float4 v = *o;
        v.x *= s; v.y *= s; v.z *= s; v.w *= s;
        *o = v;
    } else {
        *o = make_float4(0.f, 0.f, 0.f, 0.f);
    }
}

__global__ void scatter_k(const int* __restrict__ ebev, float* __restrict__ out) {
    int idx = blockIdx.x * 256 + threadIdx.x;
    if (idx >= 512 * 512) return;
    int b = idx >> 9;
    float val = (1.f - g_pgen[b]) * g_ct[idx];
    atomicAdd(out + (size_t)b * EXTV_ + ebev[idx], val);
}

__global__ void copy_k(const float* __restrict__ src, float* __restrict__ dst, int n) {
    int i = blockIdx.x * 256 + threadIdx.x;
    if (i < n) dst[i] = src[i];
}

// ---------------- host-side symbol address helper ----------------
template <typename T>
static void* symaddr_(const T& sym) {
    void* p = nullptr;
    cudaGetSymbolAddress(&p, sym);
    return p;
}

// ---------------- host launcher ----------------
extern "C" void kernel_launch(void* const* d_in, const int* in_sizes, int n_in,
                              void* d_out, int out_size) {
    const int*   y    = (const int*)  d_in[0];
    const float* h0   = (const float*)d_in[1];
    const float* c0   = (const float*)d_in[2];
    const float* enc  = (const float*)d_in[3];
    const float* ct1  = (const float*)d_in[6];
    const int*   ebev = (const int*)  d_in[8];
    const float* cov  = (const float*)d_in[9];

    int wb = 10;
    for (int i = 10; i < n_in; i++) {
        if (in_sizes[i] == 6400000) { wb = i; break; }
    }
    const float* embW = (const float*)d_in[wb + 0];
    const float* xcW  = (const float*)d_in[wb + 1];
    const float* xcb  = (const float*)d_in[wb + 2];
    const float* Wih  = (const float*)d_in[wb + 3];
    const float* Whh  = (const float*)d_in[wb + 4];
    const float* bih  = (const float*)d_in[wb + 5];
    const float* bhh  = (const float*)d_in[wb + 6];
    const float* Wq   = (const float*)d_in[wb + 7];
    const float* Wk   = (const float*)d_in[wb + 8];
    const float* Wv   = (const float*)d_in[wb + 9];
    const float* Wo   = (const float*)d_in[wb + 10];
    const float* pgW  = (const float*)d_in[wb + 11];
    const float* pgb  = (const float*)d_in[wb + 12];
    const float* o1W  = (const float*)d_in[wb + 13];
    const float* o1b  = (const float*)d_in[wb + 14];
    const float* o2W  = (const float*)d_in[wb + 15];
    const float* o2b  = (const float*)d_in[wb + 16];
    float* out = (float*)d_out;
    const bool full = (out_size >= OUT_FULL);

    float* p_qk   = (float*)symaddr_(g_qk);
    __nv_bfloat16* p_A3 = (__nv_bfloat16*)symaddr_(g_A3);
    __nv_bfloat16* p_B3 = (__nv_bfloat16*)symaddr_(g_B3);
    float* p_wgT  = (float*)symaddr_(g_wgT);
    float* p_xcWT = (float*)symaddr_(g_xcWT);
    float* p_o1WT = (float*)symaddr_(g_o1WT);
    float* p_wvT  = (float*)symaddr_(g_wvT);
    float* p_woT  = (float*)symaddr_(g_woT);
    float* p_o2WT = (float*)symaddr_(g_o2WT);
    float* p_cat1 = (float*)symaddr_(g_cat1);
    float* p_x    = (float*)symaddr_(g_x);
    float* p_cat2 = (float*)symaddr_(g_cat2);
    float* p_gates= (float*)symaddr_(g_gates);
    float* p_pool = (float*)symaddr_(g_pooled);
    float* p_ct   = (float*)symaddr_(g_ct);
    float* p_cat3 = (float*)symaddr_(g_cat3);
    float* p_out1 = (float*)symaddr_(g_out1);

    cudaFuncSetAttribute(attn_pool2_k, cudaFuncAttributeMaxDynamicSharedMemorySize, ATTN_SMEM);
    cudaFuncSetAttribute(qk_mma_k, cudaFuncAttributeMaxDynamicSharedMemorySize, QK_SMEM);

    // launches 1-3, then qk_mma_k at slot 4 (the launch ncu profiles)
    buildA3_k<<<131072, 256>>>(enc, p_A3);
    buildB3_k<<<2048, 256>>>(Wq, Wk, p_B3);
    build_wgT_k<<<1536, 256>>>(Wih, Whh);
    qk_mma_k<<<dim3(16, 512), 128, QK_SMEM>>>(p_A3, p_B3, p_qk);
    attn_pool2_k<<<dim3(8, 512), 256, ATTN_SMEM>>>(p_qk, enc);

    // weight reshapes/transposes
    transpose_k<<<dim3(20, 4),   dim3(32, 8)>>>(xcW, p_xcWT, 128, 640);
    transpose_k<<<dim3(24, 8),   dim3(32, 8)>>>(o1W, p_o1WT, 256, 768);
    transpose_k<<<dim3(16, 16),  dim3(32, 8)>>>(Wv, p_wvT, 512, 512);
    transpose_k<<<dim3(16, 16),  dim3(32, 8)>>>(Wo, p_woT, 512, 512);
    transpose_k<<<dim3(8, 1563), dim3(32, 8)>>>(o2W, p_o2WT, 50000, 256);

    // embedding + x projection
    cat1_k<<<1280, 256>>>(ct1, embW, y);
    dense8_k<<<dim3(1, 64), 256>>>(p_cat1, p_xcWT, xcb, nullptr, p_x, 640, 128);

    // LSTM
    cat2_k<<<768, 256>>>(h0);
    dense8_k<<<dim3(4, 64), 256>>>(p_cat2, p_wgT, bih, bhh, p_gates, 384, 1024);
    lstm_k<<<512, 256>>>(c0, full ? out + OFF_H : nullptr, full ? out + OFF_C : nullptr);

    // attention tail: per-head Wv fold + Wo
    wv_head_k<<<dim3(4, 64), 128>>>();
    dense8_k<<<dim3(2, 64), 256>>>(p_pool, p_woT, nullptr, nullptr, p_ct, 512, 512);

    // pointer gate
    pgen_k<<<512, 128>>>(pgW, pgb, full ? out + OFF_PG : nullptr);

    // vocab head
    cat3_k<<<1536, 256>>>();
    dense8_k<<<dim3(1, 64), 256>>>(p_cat3, p_o1WT, o1b, nullptr, p_out1, 768, 256);
    zeroZ_k<<<1, 512>>>();
    sgemm_logits<<<dim3(391, 4), 256>>>(p_out1, p_o2WT, o2b, out, 50000, 256);

    // final distribution
    scale_k<<<25200, 256>>>(out);
    scatter_k<<<1024, 256>>>(ebev, out);

    if (full) {
        copy_k<<<1024, 256>>>(p_ct, out + OFF_CT1, 262144);
        copy_k<<<1024, 256>>>(p_ct, out + OFF_CT2, 262144);
        copy_k<<<256, 256>>>(cov, out + OFF_COV, 65536);
    }
}

// round 13
// speedup vs baseline: 1.8319x; 1.2561x over previous
#include <cuda_runtime.h>
#include <cuda_bf16.h>
#include <math.h>
#include <stdint.h>

// ---------------- problem constants ----------------
#define VV_  50000
#define EXTV_ 50400

// output offsets (flattened tuple order)
#define OFF_FD  0
#define OFF_H   25804800
#define OFF_C   25935872
#define OFF_CT1 26066944
#define OFF_CT2 26329088
#define OFF_PG  26591232
#define OFF_COV 26591744
#define OUT_FULL 26657280

// ---------------- device scratch (no cudaMalloc allowed) ----------------
__device__ float g_qk[65536 * 1024];            // Q | K per enc position (fp32)
__device__ __nv_bfloat16 g_Ab[(size_t)65536 * 512];   // bf16(enc)
__device__ __nv_bfloat16 g_Bb[1024 * 512];            // bf16([Wq;Wk]), K half pre-scaled by 1/8
__device__ float g_wgT[384 * 1024];
__device__ float g_xcWT[640 * 128];
__device__ float g_o1WT[768 * 256];
__device__ float g_wvT[512 * 512];
__device__ float g_woT[512 * 512];
__device__ float g_o2WT[256 * 50000];
__device__ float g_cat1[512 * 640];
__device__ float g_x[512 * 128];
__device__ float g_cat2[512 * 384];
__device__ float g_gates[512 * 1024];
__device__ float g_h[512 * 256];
__device__ float g_c[512 * 256];
__device__ float g_e[512 * 8 * 512];
__device__ float g_pooled[512 * 512];
__device__ float g_ct[512 * 512];
__device__ float g_cat3[512 * 768];
__device__ float g_out1[512 * 256];
__device__ float g_pgen[512];
__device__ float g_Z[512];

__device__ __forceinline__ float sigmoidf_(float x) { return 1.0f / (1.0f + __expf(-x)); }

__device__ __forceinline__ uint32_t smem_u32_(const void* p) {
    uint32_t a;
    asm("{ .reg .u64 t; cvta.to.shared.u64 t, %1; cvt.u32.u64 %0, t; }" : "=r"(a) : "l"(p));
    return a;
}

__device__ __forceinline__ void cp_async16_(uint32_t dst, const void* src) {
    asm volatile("cp.async.cg.shared.global [%0], [%1], 16;" :: "r"(dst), "l"(src));
}

// ---------------- bf16 conversion prep ----------------
__global__ void buildAb_k(const float* __restrict__ enc, __nv_bfloat16* __restrict__ A) {
    int i = blockIdx.x * 256 + threadIdx.x;
    if (i >= 65536 * 512) return;
    A[i] = __float2bfloat16(enc[i]);
}

// K rows (n >= 512) pre-scaled by 0.125 so attention skips the softmax scale
__global__ void buildBb_k(const float* __restrict__ Wq, const float* __restrict__ Wk,
                          __nv_bfloat16* __restrict__ B) {
    int i = blockIdx.x * 256 + threadIdx.x;
    if (i >= 1024 * 512) return;
    int n = i >> 9, k = i & 511;
    float v = (n < 512) ? Wq[(size_t)n * 512 + k]
                        : Wk[(size_t)(n - 512) * 512 + k] * 0.125f;
    B[i] = __float2bfloat16(v);
}

// ---------------- bf16 HMMA GEMM, 2-stage cp.async, 4-warp / 64x32 warp tile ----------------
// C[65536,1024] = A[.,512] @ B[.,512]^T  (pure bf16, K=512 -> 8 k-tiles of 64)
// block tile 128(M)x64(N); 4 warps as 2(M)x2(N); warp tile 64x32
// smem: sA [2][128][72], sB [2][64][72] bf16 = 55296 B
#define QK_SMEM ((2 * 128 * 72 + 2 * 64 * 72) * 2)
__global__ __launch_bounds__(128) void qk_mma_k(const __nv_bfloat16* __restrict__ A,
                                                const __nv_bfloat16* __restrict__ B,
                                                float* __restrict__ C) {
    extern __shared__ __nv_bfloat16 smem_bf[];
    const int tid = threadIdx.x;          // 0..127
    const int wid = tid >> 5, lane = tid & 31;
    const int wm = (wid & 1) << 6;        // 0 / 64
    const int wn = (wid >> 1) << 5;       // 0 / 32
    const int m0 = blockIdx.y << 7;
    const int n0 = blockIdx.x << 6;
    const int lr = lane & 7;
    const int lg = lane >> 3;

    const int rA = tid >> 3;              // 0..15
    const int c8 = (tid & 7) << 3;

    float acc[4][4][4];
#pragma unroll
    for (int mi = 0; mi < 4; mi++)
#pragma unroll
        for (int ni = 0; ni < 4; ni++)
#pragma unroll
            for (int r = 0; r < 4; r++) acc[mi][ni][r] = 0.f;

    // prologue: stage tile 0 into stage 0
#pragma unroll
    for (int i = 0; i < 8; i++) {
        int r = rA + (i << 4);
        cp_async16_(smem_u32_(&smem_bf[r * 72 + c8]),
                    A + (size_t)(m0 + r) * 512 + c8);
    }
#pragma unroll
    for (int i = 0; i < 4; i++) {
        int r = rA + (i << 4);
        cp_async16_(smem_u32_(&smem_bf[18432 + r * 72 + c8]),
                    B + (size_t)(n0 + r) * 512 + c8);
    }
    asm volatile("cp.async.commit_group;" ::: "memory");

    for (int kt = 0; kt < 8; kt++) {
        const int buf = kt & 1;
        if (kt < 7) {
            const int nb = (kt + 1) & 1;
            const int kof = (kt + 1) << 6;
#pragma unroll
            for (int i = 0; i < 8; i++) {
                int r = rA + (i << 4);
                cp_async16_(smem_u32_(&smem_bf[nb * 9216 + r * 72 + c8]),
                            A + (size_t)(m0 + r) * 512 + kof + c8);
            }
#pragma unroll
            for (int i = 0; i < 4; i++) {
                int r = rA + (i << 4);
                cp_async16_(smem_u32_(&smem_bf[18432 + nb * 4608 + r * 72 + c8]),
                            B + (size_t)(n0 + r) * 512 + kof + c8);
            }
            asm volatile("cp.async.commit_group;" ::: "memory");
            asm volatile("cp.async.wait_group 1;" ::: "memory");
        } else {
            asm volatile("cp.async.wait_group 0;" ::: "memory");
        }
        __syncthreads();

        const __nv_bfloat16* bufA = smem_bf + buf * 9216;
        const __nv_bfloat16* bufB = smem_bf + 18432 + buf * 4608;
#pragma unroll
        for (int ks = 0; ks < 4; ks++) {
            uint32_t af[4][4];
#pragma unroll
            for (int mi = 0; mi < 4; mi++) {
                uint32_t addr = smem_u32_(
                    bufA + (wm + (mi << 4) + lr + ((lg & 1) << 3)) * 72 + (ks << 4) + ((lg >> 1) << 3));
                asm volatile("ldmatrix.sync.aligned.m8n8.x4.shared.b16 {%0,%1,%2,%3}, [%4];"
                             : "=r"(af[mi][0]), "=r"(af[mi][1]), "=r"(af[mi][2]), "=r"(af[mi][3])
                             : "r"(addr));
            }
            uint32_t bq[2][4];
#pragma unroll
            for (int nf = 0; nf < 2; nf++) {
                uint32_t addr = smem_u32_(
                    bufB + (wn + (nf << 4) + ((lg >> 1) << 3) + lr) * 72 + (ks << 4) + ((lg & 1) << 3));
                asm volatile("ldmatrix.sync.aligned.m8n8.x4.shared.b16 {%0,%1,%2,%3}, [%4];"
                             : "=r"(bq[nf][0]), "=r"(bq[nf][1]), "=r"(bq[nf][2]), "=r"(bq[nf][3])
                             : "r"(addr));
            }
#pragma unroll
            for (int mi = 0; mi < 4; mi++)
#pragma unroll
                for (int ni = 0; ni < 4; ni++) {
                    const uint32_t b0 = bq[ni >> 1][(ni & 1) << 1];
                    const uint32_t b1 = bq[ni >> 1][((ni & 1) << 1) + 1];
                    asm volatile(
                        "mma.sync.aligned.m16n8k16.row.col.f32.bf16.bf16.f32 "
                        "{%0,%1,%2,%3}, {%4,%5,%6,%7}, {%8,%9}, {%0,%1,%2,%3};"
                        : "+f"(acc[mi][ni][0]), "+f"(acc[mi][ni][1]),
                          "+f"(acc[mi][ni][2]), "+f"(acc[mi][ni][3])
                        : "r"(af[mi][0]), "r"(af[mi][1]), "r"(af[mi][2]), "r"(af[mi][3]),
                          "r"(b0), "r"(b1));
                }
        }
        __syncthreads();
    }

    const int er = lane >> 2;
    const int ec = (lane & 3) << 1;
#pragma unroll
    for (int mi = 0; mi < 4; mi++) {
#pragma unroll
        for (int ni = 0; ni < 4; ni++) {
            size_t row = (size_t)(m0 + wm + (mi << 4) + er);
            int col = n0 + wn + (ni << 3) + ec;
            *(float2*)&C[row * 1024 + col] = make_float2(acc[mi][ni][0], acc[mi][ni][1]);
            *(float2*)&C[(row + 8) * 1024 + col] = make_float2(acc[mi][ni][2], acc[mi][ni][3]);
        }
    }
}

// ---------------- single-pass register-tiled pooled attention ----------------
#define ATTN_SMEM ((128 * 65 + 64 * 128 + 16 * 128 + 128) * 4)
__global__ __launch_bounds__(256) void attn_pool2_k(const float* __restrict__ qk,
                                                    const float* __restrict__ enc) {
    extern __shared__ float sm[];
    float* Qh   = sm;
    float* KhT  = Qh + 128 * 65;
    float* part = KhT + 64 * 128;
    float* w    = part + 16 * 128;
    const int h = blockIdx.x, b = blockIdx.y;
    const int tid = threadIdx.x;
    const int tx = tid & 15, ty = tid >> 4;

    for (int i = tid; i < 2048; i += 256) {
        int r = i >> 4, c4 = (i & 15) << 2;
        float4 v = *(const float4*)(qk + ((size_t)(b * 128 + r)) * 1024 + h * 64 + c4);
        float* dst = Qh + r * 65 + c4;
        dst[0] = v.x; dst[1] = v.y; dst[2] = v.z; dst[3] = v.w;
        float4 u = *(const float4*)(qk + ((size_t)(b * 128 + r)) * 1024 + 512 + h * 64 + c4);
        KhT[(c4 + 0) * 128 + r] = u.x;
        KhT[(c4 + 1) * 128 + r] = u.y;
        KhT[(c4 + 2) * 128 + r] = u.z;
        KhT[(c4 + 3) * 128 + r] = u.w;
    }
    __syncthreads();

    float acc[8][8];
#pragma unroll
    for (int i = 0; i < 8; i++)
#pragma unroll
        for (int j = 0; j < 8; j++) acc[i][j] = 0.f;

    for (int k = 0; k < 64; k++) {
        float a[8], bb[8];
#pragma unroll
        for (int i = 0; i < 8; i++) a[i] = Qh[(ty + (i << 4)) * 65 + k];
#pragma unroll
        for (int j = 0; j < 8; j++) bb[j] = KhT[k * 128 + tx + (j << 4)];
#pragma unroll
        for (int i = 0; i < 8; i++)
#pragma unroll
            for (int j = 0; j < 8; j++) acc[i][j] = fmaf(a[i], bb[j], acc[i][j]);
    }

    // K was pre-scaled by 1/8 in buildBb -> scores already scaled
    float rs[8];
#pragma unroll
    for (int i = 0; i < 8; i++) {
        float s = 0.f;
#pragma unroll
        for (int j = 0; j < 8; j++) {
            float e = __expf(acc[i][j]);
            acc[i][j] = e;
            s += e;
        }
        rs[i] = s;
    }
#pragma unroll
    for (int m = 1; m < 16; m <<= 1)
#pragma unroll
        for (int i = 0; i < 8; i++) rs[i] += __shfl_xor_sync(0xffffffffu, rs[i], m);

    float cs[8];
#pragma unroll
    for (int j = 0; j < 8; j++) cs[j] = 0.f;
#pragma unroll
    for (int i = 0; i < 8; i++) {
        float zi = 1.f / rs[i];
#pragma unroll
        for (int j = 0; j < 8; j++) cs[j] = fmaf(acc[i][j], zi, cs[j]);
    }
#pragma unroll
    for (int j = 0; j < 8; j++) part[ty * 128 + tx + (j << 4)] = cs[j];
    __syncthreads();

    if (tid < 128) {
        float s = 0.f;
#pragma unroll
        for (int t2 = 0; t2 < 16; t2++) s += part[t2 * 128 + tid];
        w[tid] = s * (1.f / 128.f);
    }
    __syncthreads();

    float ea0 = 0.f, ea1 = 0.f;
    const float* encb = enc + (size_t)b * 128 * 512;
    for (int t = 0; t < 128; t++) {
        float wt = w[t];
        ea0 = fmaf(wt, encb[t * 512 + tid], ea0);
        ea1 = fmaf(wt, encb[t * 512 + tid + 256], ea1);
    }
    float* eo = g_e + ((size_t)b * 8 + h) * 512;
    eo[tid] = ea0;
    eo[tid + 256] = ea1;
}

// ---------------- weight prep kernels ----------------
__global__ void build_wgT_k(const float* __restrict__ Wih, const float* __restrict__ Whh) {
    int idx = blockIdx.x * 256 + threadIdx.x;
    if (idx >= 384 * 1024) return;
    int j = idx >> 10, r = idx & 1023;
    g_wgT[idx] = (j < 128) ? Wih[(size_t)r * 128 + j] : Whh[(size_t)r * 256 + (j - 128)];
}

__global__ void transpose_k(const float* __restrict__ in, float* __restrict__ out, int R, int C) {
    __shared__ float t[32][33];
    int c0 = blockIdx.x << 5, r0 = blockIdx.y << 5;
    int c = c0 + threadIdx.x;
    for (int i = threadIdx.y; i < 32; i += 8) {
        int r = r0 + i;
        if (r < R && c < C) t[i][threadIdx.x] = in[(size_t)r * C + c];
    }
    __syncthreads();
    int rr = r0 + threadIdx.x;
    for (int i = threadIdx.y; i < 32; i += 8) {
        int cc = c0 + i;
        if (cc < C && rr < R) out[(size_t)cc * R + rr] = t[threadIdx.x][i];
    }
}

// ---------------- concat builders ----------------
__global__ void cat1_k(const float* __restrict__ ct1, const float* __restrict__ embW,
                       const int* __restrict__ y) {
    int idx = blockIdx.x * 256 + threadIdx.x;
    if (idx >= 512 * 640) return;
    int b = idx / 640, j = idx - b * 640;
    g_cat1[idx] = (j < 512) ? ct1[(size_t)b * 512 + j]
                            : embW[(size_t)y[b] * 128 + (j - 512)];
}

__global__ void cat2_k(const float* __restrict__ h0) {
    int idx = blockIdx.x * 256 + threadIdx.x;
    if (idx >= 512 * 384) return;
    int b = idx / 384, j = idx - b * 384;
    g_cat2[idx] = (j < 128) ? g_x[b * 128 + j] : h0[(size_t)b * 256 + (j - 128)];
}

__global__ void cat3_k() {
    int idx = blockIdx.x * 256 + threadIdx.x;
    if (idx >= 512 * 768) return;
    int b = idx / 768, j = idx - b * 768;
    g_cat3[idx] = (j < 256) ? g_h[b * 256 + j] : g_ct[b * 512 + (j - 256)];
}

// ---------------- small dense ----------------
__global__ __launch_bounds__(256) void dense8_k(const float* __restrict__ X,
                                                const float* __restrict__ Wt,
                                                const float* __restrict__ b1,
                                                const float* __restrict__ b2,
                                                float* __restrict__ Y, int K, int N) {
    __shared__ float xs[8 * 768];
    const int tid = threadIdx.x;
    const int m0 = blockIdx.y << 3;
    const int col = (blockIdx.x << 8) + tid;
    for (int i = tid; i < (K << 3); i += 256) {
        int r = i / K, j = i - r * K;
        xs[i] = X[(size_t)(m0 + r) * K + j];
    }
    __syncthreads();
    if (col >= N) return;
    float acc[8];
#pragma unroll
    for (int r = 0; r < 8; r++) acc[r] = 0.f;
#pragma unroll 4
    for (int j = 0; j < K; j++) {
        float w = Wt[(size_t)j * N + col];
#pragma unroll
        for (int r = 0; r < 8; r++) acc[r] = fmaf(xs[r * K + j], w, acc[r]);
    }
    float bb = (b1 ? b1[col] : 0.f) + (b2 ? b2[col] : 0.f);
#pragma unroll
    for (int r = 0; r < 8; r++) Y[(size_t)(m0 + r) * N + col] = acc[r] + bb;
}

// ---------------- LSTM pointwise ----------------
__global__ void lstm_k(const float* __restrict__ c0, float* __restrict__ outH, float* __restrict__ outC) {
    int i = blockIdx.x * 256 + threadIdx.x;
    if (i >= 512 * 256) return;
    int b = i >> 8, u = i & 255;
    const float* g = &g_gates[b * 1024];
    float ig = sigmoidf_(g[u]);
    float fg = sigmoidf_(g[256 + u]);
    float gg = tanhf(g[512 + u]);
    float og = sigmoidf_(g[768 + u]);
    float cn = fg * c0[i] + ig * gg;
    float hn = og * tanhf(cn);
    g_h[i] = hn;
    g_c[i] = cn;
    if (outH) outH[i] = hn;
    if (outC) outC[i] = cn;
}

// ---------------- logits SGEMM fused with exp + row-sum ----------------
__global__ __launch_bounds__(256) void sgemm_logits(const float* __restrict__ A, const float* __restrict__ Bm,
                                                    const float* __restrict__ bias,
                                                    float* __restrict__ outE, int N, int K) {
    __shared__ float As[16][128];
    __shared__ float Bs[16][128];
    const int tid = threadIdx.x;
    const int tx = tid & 15, ty = tid >> 4;
    const int bm = blockIdx.y << 7, bn = blockIdx.x << 7;
    float acc[8][8];
#pragma unroll
    for (int i = 0; i < 8; i++)
#pragma unroll
        for (int j = 0; j < 8; j++) acc[i][j] = 0.f;

    for (int k0 = 0; k0 < K; k0 += 16) {
#pragma unroll
        for (int uu = 0; uu < 2; uu++) {
            int u = tid + (uu << 8);
            int r = u >> 2, kq = u & 3;
            float4 v = *reinterpret_cast<const float4*>(A + (size_t)(bm + r) * K + k0 + (kq << 2));
            As[(kq << 2) + 0][r] = v.x;
            As[(kq << 2) + 1][r] = v.y;
            As[(kq << 2) + 2][r] = v.z;
            As[(kq << 2) + 3][r] = v.w;
        }
#pragma unroll
        for (int uu = 0; uu < 2; uu++) {
            int u = tid + (uu << 8);
            int kr = u >> 5, nq = u & 31;
            int colb = bn + (nq << 2);
            const float* src = Bm + (size_t)(k0 + kr) * N;
            float4 v;
            if (colb + 3 < N) {
                v = *reinterpret_cast<const float4*>(src + colb);
            } else {
                v.x = (colb + 0 < N) ? src[colb + 0] : 0.f;
                v.y = (colb + 1 < N) ? src[colb + 1] : 0.f;
                v.z = (colb + 2 < N) ? src[colb + 2] : 0.f;
                v.w = (colb + 3 < N) ? src[colb + 3] : 0.f;
            }
            *reinterpret_cast<float4*>(&Bs[kr][nq << 2]) = v;
        }
        __syncthreads();
#pragma unroll
        for (int kk = 0; kk < 16; kk++) {
            float a[8], bv[8];
            *(float4*)&a[0] = *(const float4*)&As[kk][ty << 3];
            *(float4*)&a[4] = *(const float4*)&As[kk][(ty << 3) + 4];
            *(float4*)&bv[0] = *(const float4*)&Bs[kk][tx << 3];
            *(float4*)&bv[4] = *(const float4*)&Bs[kk][(tx << 3) + 4];
#pragma unroll
            for (int i = 0; i < 8; i++)
#pragma unroll
                for (int j = 0; j < 8; j++) acc[i][j] = fmaf(a[i], bv[j], acc[i][j]);
        }
        __syncthreads();
    }
#pragma unroll
    for (int i = 0; i < 8; i++) {
        int row = bm + (ty << 3) + i;
        float rs = 0.f;
        float* orow = outE + (size_t)row * EXTV_;
#pragma unroll
        for (int j = 0; j < 8; j++) {
            int col = bn + (tx << 3) + j;
            if (col < N) {
                float e = __expf(acc[i][j] + bias[col]);
                orow[col] = e;
                rs += e;
            }
        }
#pragma unroll
        for (int m = 1; m < 16; m <<= 1) rs += __shfl_xor_sync(0xffffffffu, rs, m);
        if (tx == 0) atomicAdd(&g_Z[row], rs);
    }
}

// ---------------- per-head Wv fold ----------------
__global__ __launch_bounds__(128) void wv_head_k() {
    __shared__ float es[8 * 2 * 512];
    const int tid = threadIdx.x;
    const int cx = blockIdx.x;
    const int b0 = blockIdx.y << 3;
    const int hbase = cx << 1;

    for (int i = tid; i < 8 * 2 * 512; i += 128) {
        int bb = i >> 10;
        int rem = i & 1023;
        int hh = rem >> 9;
        int j = rem & 511;
        es[i] = g_e[((size_t)(b0 + bb) * 8 + hbase + hh) * 512 + j];
    }
    __syncthreads();

    const int col = (cx << 7) + tid;
    const int hh = tid >> 6;
    float acc[8];
#pragma unroll
    for (int bb = 0; bb < 8; bb++) acc[bb] = 0.f;
    for (int j = 0; j < 512; j++) {
        float w0 = g_wvT[(size_t)j * 512 + col];
#pragma unroll
        for (int bb = 0; bb < 8; bb++)
            acc[bb] = fmaf(es[(bb << 10) + (hh << 9) + j], w0, acc[bb]);
    }
#pragma unroll
    for (int bb = 0; bb < 8; bb++)
        g_pooled[(size_t)(b0 + bb) * 512 + col] = acc[bb];
}

// ---------------- pointer gate ----------------
__global__ void pgen_k(const float* __restrict__ pgW, const float* __restrict__ pgb,
                       float* __restrict__ outPG) {
    int b = blockIdx.x;
    int tid = threadIdx.x;
    float s = 0.f;
    for (int j = tid; j < 1152; j += 128) {
        float v;
        if (j < 512)       v = g_ct[b * 512 + j];
        else if (j < 768)  v = g_h[b * 256 + (j - 512)];
        else if (j < 1024) v = g_c[b * 256 + (j - 768)];
        else               v = g_x[b * 128 + (j - 1024)];
        s += v * pgW[j];
    }
    __shared__ float red[128];
    red[tid] = s;
    __syncthreads();
    for (int off = 64; off; off >>= 1) {
        if (tid < off) red[tid] += red[tid + off];
        __syncthreads();
    }
    if (tid == 0) {
        float p = sigmoidf_(red[0] + pgb[0]);
        g_pgen[b] = p;
        if (outPG) outPG[b] = p;
    }
}

// ---------------- final distribution ----------------
__global__ void zeroZ_k() {
    int i = threadIdx.x;
    if (i < 512) g_Z[i] = 0.f;
}

__global__ void scale_k(float* __restrict__ out) {
    int i = blockIdx.x * 256 + threadIdx.x;
    if (i >= 512 * 12600) return;
    int b = i / 12600, r4 = i - b * 12600;
    float4* o = (float4*)out + (size_t)b * 12600 + r4;
    if (r4 < 12500) {
        float s = g_pgen[b] / g_Z[b];
        float4 v = *o;
        v.x *= s; v.y *= s; v.z *= s; v.w *= s;
        *o = v;
    } else {
        *o = make_float4(0.f, 0.f, 0.f, 0.f);
    }
}

__global__ void scatter_k(const int* __restrict__ ebev, float* __restrict__ out) {
    int idx = blockIdx.x * 256 + threadIdx.x;
    if (idx >= 512 * 512) return;
    int b = idx >> 9;
    float val = (1.f - g_pgen[b]) * g_ct[idx];
    atomicAdd(out + (size_t)b * EXTV_ + ebev[idx], val);
}

__global__ void copy_k(const float* __restrict__ src, float* __restrict__ dst, int n) {
    int i = blockIdx.x * 256 + threadIdx.x;
    if (i < n) dst[i] = src[i];
}

// ---------------- host-side symbol address helper ----------------
template <typename T>
static void* symaddr_(const T& sym) {
    void* p = nullptr;
    cudaGetSymbolAddress(&p, sym);
    return p;
}

// ---------------- host launcher ----------------
extern "C" void kernel_launch(void* const* d_in, const int* in_sizes, int n_in,
                              void* d_out, int out_size) {
    const int*   y    = (const int*)  d_in[0];
    const float* h0   = (const float*)d_in[1];
    const float* c0   = (const float*)d_in[2];
    const float* enc  = (const float*)d_in[3];
    const float* ct1  = (const float*)d_in[6];
    const int*   ebev = (const int*)  d_in[8];
    const float* cov  = (const float*)d_in[9];

    int wb = 10;
    for (int i = 10; i < n_in; i++) {
        if (in_sizes[i] == 6400000) { wb = i; break; }
    }
    const float* embW = (const float*)d_in[wb + 0];
    const float* xcW  = (const float*)d_in[wb + 1];
    const float* xcb  = (const float*)d_in[wb + 2];
    const float* Wih  = (const float*)d_in[wb + 3];
    const float* Whh  = (const float*)d_in[wb + 4];
    const float* bih  = (const float*)d_in[wb + 5];
    const float* bhh  = (const float*)d_in[wb + 6];
    const float* Wq   = (const float*)d_in[wb + 7];
    const float* Wk   = (const float*)d_in[wb + 8];
    const float* Wv   = (const float*)d_in[wb + 9];
    const float* Wo   = (const float*)d_in[wb + 10];
    const float* pgW  = (const float*)d_in[wb + 11];
    const float* pgb  = (const float*)d_in[wb + 12];
    const float* o1W  = (const float*)d_in[wb + 13];
    const float* o1b  = (const float*)d_in[wb + 14];
    const float* o2W  = (const float*)d_in[wb + 15];
    const float* o2b  = (const float*)d_in[wb + 16];
    float* out = (float*)d_out;
    const bool full = (out_size >= OUT_FULL);

    float* p_qk   = (float*)symaddr_(g_qk);
    __nv_bfloat16* p_Ab = (__nv_bfloat16*)symaddr_(g_Ab);
    __nv_bfloat16* p_Bb = (__nv_bfloat16*)symaddr_(g_Bb);
    float* p_wgT  = (float*)symaddr_(g_wgT);
    float* p_xcWT = (float*)symaddr_(g_xcWT);
    float* p_o1WT = (float*)symaddr_(g_o1WT);
    float* p_wvT  = (float*)symaddr_(g_wvT);
    float* p_woT  = (float*)symaddr_(g_woT);
    float* p_o2WT = (float*)symaddr_(g_o2WT);
    float* p_cat1 = (float*)symaddr_(g_cat1);
    float* p_x    = (float*)symaddr_(g_x);
    float* p_cat2 = (float*)symaddr_(g_cat2);
    float* p_gates= (float*)symaddr_(g_gates);
    float* p_pool = (float*)symaddr_(g_pooled);
    float* p_ct   = (float*)symaddr_(g_ct);
    float* p_cat3 = (float*)symaddr_(g_cat3);
    float* p_out1 = (float*)symaddr_(g_out1);

    cudaFuncSetAttribute(attn_pool2_k, cudaFuncAttributeMaxDynamicSharedMemorySize, ATTN_SMEM);
    cudaFuncSetAttribute(qk_mma_k, cudaFuncAttributeMaxDynamicSharedMemorySize, QK_SMEM);

    // launches 1-3, then qk_mma_k at slot 4 (the launch ncu profiles)
    buildAb_k<<<131072, 256>>>(enc, p_Ab);
    buildBb_k<<<2048, 256>>>(Wq, Wk, p_Bb);
    build_wgT_k<<<1536, 256>>>(Wih, Whh);
    qk_mma_k<<<dim3(16, 512), 128, QK_SMEM>>>(p_Ab, p_Bb, p_qk);
    attn_pool2_k<<<dim3(8, 512), 256, ATTN_SMEM>>>(p_qk, enc);

    // weight reshapes/transposes
    transpose_k<<<dim3(20, 4),   dim3(32, 8)>>>(xcW, p_xcWT, 128, 640);
    transpose_k<<<dim3(24, 8),   dim3(32, 8)>>>(o1W, p_o1WT, 256, 768);
    transpose_k<<<dim3(16, 16),  dim3(32, 8)>>>(Wv, p_wvT, 512, 512);
    transpose_k<<<dim3(16, 16),  dim3(32, 8)>>>(Wo, p_woT, 512, 512);
    transpose_k<<<dim3(8, 1563), dim3(32, 8)>>>(o2W, p_o2WT, 50000, 256);

    // embedding + x projection
    cat1_k<<<1280, 256>>>(ct1, embW, y);
    dense8_k<<<dim3(1, 64), 256>>>(p_cat1, p_xcWT, xcb, nullptr, p_x, 640, 128);

    // LSTM
    cat2_k<<<768, 256>>>(h0);
    dense8_k<<<dim3(4, 64), 256>>>(p_cat2, p_wgT, bih, bhh, p_gates, 384, 1024);
    lstm_k<<<512, 256>>>(c0, full ? out + OFF_H : nullptr, full ? out + OFF_C : nullptr);

    // attention tail: per-head Wv fold + Wo
    wv_head_k<<<dim3(4, 64), 128>>>();
    dense8_k<<<dim3(2, 64), 256>>>(p_pool, p_woT, nullptr, nullptr, p_ct, 512, 512);

    // pointer gate
    pgen_k<<<512, 128>>>(pgW, pgb, full ? out + OFF_PG : nullptr);

    // vocab head
    cat3_k<<<1536, 256>>>();
    dense8_k<<<dim3(1, 64), 256>>>(p_cat3, p_o1WT, o1b, nullptr, p_out1, 768, 256);
    zeroZ_k<<<1, 512>>>();
    sgemm_logits<<<dim3(391, 4), 256>>>(p_out1, p_o2WT, o2b, out, 50000, 256);

    // final distribution
    scale_k<<<25200, 256>>>(out);
    scatter_k<<<1024, 256>>>(ebev, out);

    if (full) {
        copy_k<<<1024, 256>>>(p_ct, out + OFF_CT1, 262144);
        copy_k<<<1024, 256>>>(p_ct, out + OFF_CT2, 262144);
        copy_k<<<256, 256>>>(cov, out + OFF_COV, 65536);
    }
}

// round 14
// speedup vs baseline: 2.5343x; 1.3834x over previous
#include <cuda_runtime.h>
#include <cuda_bf16.h>
#include <math.h>
#include <stdint.h>

// ---------------- problem constants ----------------
#define VV_  50000
#define EXTV_ 50400
#define VPAD_ 50048   // 64-aligned padded vocab

// output offsets (flattened tuple order)
#define OFF_FD  0
#define OFF_H   25804800
#define OFF_C   25935872
#define OFF_CT1 26066944
#define OFF_CT2 26329088
#define OFF_PG  26591232
#define OFF_COV 26591744
#define OUT_FULL 26657280

// ---------------- device scratch (no cudaMalloc allowed) ----------------
__device__ float g_qk[65536 * 1024];            // Q | K per enc position (fp32)
__device__ __nv_bfloat16 g_Ab[(size_t)65536 * 512];   // bf16(enc)
__device__ __nv_bfloat16 g_Bb[1024 * 512];            // bf16([Wq;Wk]), K half pre-scaled by 1/8
__device__ __nv_bfloat16 g_o2b[(size_t)VPAD_ * 256];  // bf16(o2W), zero-padded rows
__device__ __nv_bfloat16 g_out1b[512 * 256];          // bf16(out1)
__device__ float g_wgT[384 * 1024];
__device__ float g_xcWT[640 * 128];
__device__ float g_o1WT[768 * 256];
__device__ float g_wvT[512 * 512];
__device__ float g_woT[512 * 512];
__device__ float g_cat1[512 * 640];
__device__ float g_x[512 * 128];
__device__ float g_cat2[512 * 384];
__device__ float g_gates[512 * 1024];
__device__ float g_h[512 * 256];
__device__ float g_c[512 * 256];
__device__ float g_e[512 * 8 * 512];
__device__ float g_pooled[512 * 512];
__device__ float g_ct[512 * 512];
__device__ float g_cat3[512 * 768];
__device__ float g_out1[512 * 256];
__device__ float g_pgen[512];
__device__ float g_Z[512];

__device__ __forceinline__ float sigmoidf_(float x) { return 1.0f / (1.0f + __expf(-x)); }

__device__ __forceinline__ uint32_t smem_u32_(const void* p) {
    uint32_t a;
    asm("{ .reg .u64 t; cvta.to.shared.u64 t, %1; cvt.u32.u64 %0, t; }" : "=r"(a) : "l"(p));
    return a;
}

__device__ __forceinline__ void cp_async16_(uint32_t dst, const void* src) {
    asm volatile("cp.async.cg.shared.global [%0], [%1], 16;" :: "r"(dst), "l"(src));
}

// ---------------- bf16 conversion prep ----------------
__global__ void buildAb_k(const float* __restrict__ enc, __nv_bfloat16* __restrict__ A) {
    int i = blockIdx.x * 256 + threadIdx.x;
    if (i >= 65536 * 512) return;
    A[i] = __float2bfloat16(enc[i]);
}

// K rows (n >= 512) pre-scaled by 0.125 so attention skips the softmax scale
__global__ void buildBb_k(const float* __restrict__ Wq, const float* __restrict__ Wk,
                          __nv_bfloat16* __restrict__ B) {
    int i = blockIdx.x * 256 + threadIdx.x;
    if (i >= 1024 * 512) return;
    int n = i >> 9, k = i & 511;
    float v = (n < 512) ? Wq[(size_t)n * 512 + k]
                        : Wk[(size_t)(n - 512) * 512 + k] * 0.125f;
    B[i] = __float2bfloat16(v);
}

__global__ void buildO2b_k(const float* __restrict__ o2W, __nv_bfloat16* __restrict__ B) {
    int i = blockIdx.x * 256 + threadIdx.x;
    if (i >= VPAD_ * 256) return;
    int r = i >> 8;
    B[i] = (r < VV_) ? __float2bfloat16(o2W[(size_t)r * 256 + (i & 255)]) : __nv_bfloat16(0.f);
}

__global__ void build_out1b_k() {
    int i = blockIdx.x * 256 + threadIdx.x;
    if (i >= 512 * 256) return;
    g_out1b[i] = __float2bfloat16(g_out1[i]);
}

// ---------------- bf16 HMMA GEMM, 2-stage cp.async, 4-warp / 64x32 warp tile ----------------
// C[65536,1024] = A[.,512] @ B[.,512]^T  (pure bf16, K=512 -> 8 k-tiles of 64)
#define QK_SMEM ((2 * 128 * 72 + 2 * 64 * 72) * 2)
__global__ __launch_bounds__(128) void qk_mma_k(const __nv_bfloat16* __restrict__ A,
                                                const __nv_bfloat16* __restrict__ B,
                                                float* __restrict__ C) {
    extern __shared__ __nv_bfloat16 smem_bf[];
    const int tid = threadIdx.x;
    const int wid = tid >> 5, lane = tid & 31;
    const int wm = (wid & 1) << 6;
    const int wn = (wid >> 1) << 5;
    const int m0 = blockIdx.y << 7;
    const int n0 = blockIdx.x << 6;
    const int lr = lane & 7;
    const int lg = lane >> 3;

    const int rA = tid >> 3;
    const int c8 = (tid & 7) << 3;

    float acc[4][4][4];
#pragma unroll
    for (int mi = 0; mi < 4; mi++)
#pragma unroll
        for (int ni = 0; ni < 4; ni++)
#pragma unroll
            for (int r = 0; r < 4; r++) acc[mi][ni][r] = 0.f;

#pragma unroll
    for (int i = 0; i < 8; i++) {
        int r = rA + (i << 4);
        cp_async16_(smem_u32_(&smem_bf[r * 72 + c8]), A + (size_t)(m0 + r) * 512 + c8);
    }
#pragma unroll
    for (int i = 0; i < 4; i++) {
        int r = rA + (i << 4);
        cp_async16_(smem_u32_(&smem_bf[18432 + r * 72 + c8]), B + (size_t)(n0 + r) * 512 + c8);
    }
    asm volatile("cp.async.commit_group;" ::: "memory");

    for (int kt = 0; kt < 8; kt++) {
        const int buf = kt & 1;
        if (kt < 7) {
            const int nb = (kt + 1) & 1;
            const int kof = (kt + 1) << 6;
#pragma unroll
            for (int i = 0; i < 8; i++) {
                int r = rA + (i << 4);
                cp_async16_(smem_u32_(&smem_bf[nb * 9216 + r * 72 + c8]),
                            A + (size_t)(m0 + r) * 512 + kof + c8);
            }
#pragma unroll
            for (int i = 0; i < 4; i++) {
                int r = rA + (i << 4);
                cp_async16_(smem_u32_(&smem_bf[18432 + nb * 4608 + r * 72 + c8]),
                            B + (size_t)(n0 + r) * 512 + kof + c8);
            }
            asm volatile("cp.async.commit_group;" ::: "memory");
            asm volatile("cp.async.wait_group 1;" ::: "memory");
        } else {
            asm volatile("cp.async.wait_group 0;" ::: "memory");
        }
        __syncthreads();

        const __nv_bfloat16* bufA = smem_bf + buf * 9216;
        const __nv_bfloat16* bufB = smem_bf + 18432 + buf * 4608;
#pragma unroll
        for (int ks = 0; ks < 4; ks++) {
            uint32_t af[4][4];
#pragma unroll
            for (int mi = 0; mi < 4; mi++) {
                uint32_t addr = smem_u32_(
                    bufA + (wm + (mi << 4) + lr + ((lg & 1) << 3)) * 72 + (ks << 4) + ((lg >> 1) << 3));
                asm volatile("ldmatrix.sync.aligned.m8n8.x4.shared.b16 {%0,%1,%2,%3}, [%4];"
                             : "=r"(af[mi][0]), "=r"(af[mi][1]), "=r"(af[mi][2]), "=r"(af[mi][3])
                             : "r"(addr));
            }
            uint32_t bq[2][4];
#pragma unroll
            for (int nf = 0; nf < 2; nf++) {
                uint32_t addr = smem_u32_(
                    bufB + (wn + (nf << 4) + ((lg >> 1) << 3) + lr) * 72 + (ks << 4) + ((lg & 1) << 3));
                asm volatile("ldmatrix.sync.aligned.m8n8.x4.shared.b16 {%0,%1,%2,%3}, [%4];"
                             : "=r"(bq[nf][0]), "=r"(bq[nf][1]), "=r"(bq[nf][2]), "=r"(bq[nf][3])
                             : "r"(addr));
            }
#pragma unroll
            for (int mi = 0; mi < 4; mi++)
#pragma unroll
                for (int ni = 0; ni < 4; ni++) {
                    const uint32_t b0 = bq[ni >> 1][(ni & 1) << 1];
                    const uint32_t b1 = bq[ni >> 1][((ni & 1) << 1) + 1];
                    asm volatile(
                        "mma.sync.aligned.m16n8k16.row.col.f32.bf16.bf16.f32 "
                        "{%0,%1,%2,%3}, {%4,%5,%6,%7}, {%8,%9}, {%0,%1,%2,%3};"
                        : "+f"(acc[mi][ni][0]), "+f"(acc[mi][ni][1]),
                          "+f"(acc[mi][ni][2]), "+f"(acc[mi][ni][3])
                        : "r"(af[mi][0]), "r"(af[mi][1]), "r"(af[mi][2]), "r"(af[mi][3]),
                          "r"(b0), "r"(b1));
                }
        }
        __syncthreads();
    }

    const int er = lane >> 2;
    const int ec = (lane & 3) << 1;
#pragma unroll
    for (int mi = 0; mi < 4; mi++) {
#pragma unroll
        for (int ni = 0; ni < 4; ni++) {
            size_t row = (size_t)(m0 + wm + (mi << 4) + er);
            int col = n0 + wn + (ni << 3) + ec;
            *(float2*)&C[row * 1024 + col] = make_float2(acc[mi][ni][0], acc[mi][ni][1]);
            *(float2*)&C[(row + 8) * 1024 + col] = make_float2(acc[mi][ni][2], acc[mi][ni][3]);
        }
    }
}

// ---------------- bf16 HMMA logits GEMM fused with exp + bias + row-sum ----------------
// outE rows: exp(out1 @ o2W^T + bias); A = g_out1b [512,256], B = g_o2b [50048,256]
// block tile 128(M)x64(N), grid (782, 4); K=256 -> 4 k-tiles
__global__ __launch_bounds__(128) void logits_mma_k(const __nv_bfloat16* __restrict__ A,
                                                    const __nv_bfloat16* __restrict__ B,
                                                    const float* __restrict__ bias,
                                                    float* __restrict__ outE) {
    extern __shared__ __nv_bfloat16 smem_bf[];
    const int tid = threadIdx.x;
    const int wid = tid >> 5, lane = tid & 31;
    const int wm = (wid & 1) << 6;
    const int wn = (wid >> 1) << 5;
    const int m0 = blockIdx.y << 7;
    const int n0 = blockIdx.x << 6;
    const int lr = lane & 7;
    const int lg = lane >> 3;

    const int rA = tid >> 3;
    const int c8 = (tid & 7) << 3;

    float acc[4][4][4];
#pragma unroll
    for (int mi = 0; mi < 4; mi++)
#pragma unroll
        for (int ni = 0; ni < 4; ni++)
#pragma unroll
            for (int r = 0; r < 4; r++) acc[mi][ni][r] = 0.f;

#pragma unroll
    for (int i = 0; i < 8; i++) {
        int r = rA + (i << 4);
        cp_async16_(smem_u32_(&smem_bf[r * 72 + c8]), A + (size_t)(m0 + r) * 256 + c8);
    }
#pragma unroll
    for (int i = 0; i < 4; i++) {
        int r = rA + (i << 4);
        cp_async16_(smem_u32_(&smem_bf[18432 + r * 72 + c8]), B + (size_t)(n0 + r) * 256 + c8);
    }
    asm volatile("cp.async.commit_group;" ::: "memory");

    for (int kt = 0; kt < 4; kt++) {
        const int buf = kt & 1;
        if (kt < 3) {
            const int nb = (kt + 1) & 1;
            const int kof = (kt + 1) << 6;
#pragma unroll
            for (int i = 0; i < 8; i++) {
                int r = rA + (i << 4);
                cp_async16_(smem_u32_(&smem_bf[nb * 9216 + r * 72 + c8]),
                            A + (size_t)(m0 + r) * 256 + kof + c8);
            }
#pragma unroll
            for (int i = 0; i < 4; i++) {
                int r = rA + (i << 4);
                cp_async16_(smem_u32_(&smem_bf[18432 + nb * 4608 + r * 72 + c8]),
                            B + (size_t)(n0 + r) * 256 + kof + c8);
            }
            asm volatile("cp.async.commit_group;" ::: "memory");
            asm volatile("cp.async.wait_group 1;" ::: "memory");
        } else {
            asm volatile("cp.async.wait_group 0;" ::: "memory");
        }
        __syncthreads();

        const __nv_bfloat16* bufA = smem_bf + buf * 9216;
        const __nv_bfloat16* bufB = smem_bf + 18432 + buf * 4608;
#pragma unroll
        for (int ks = 0; ks < 4; ks++) {
            uint32_t af[4][4];
#pragma unroll
            for (int mi = 0; mi < 4; mi++) {
                uint32_t addr = smem_u32_(
                    bufA + (wm + (mi << 4) + lr + ((lg & 1) << 3)) * 72 + (ks << 4) + ((lg >> 1) << 3));
                asm volatile("ldmatrix.sync.aligned.m8n8.x4.shared.b16 {%0,%1,%2,%3}, [%4];"
                             : "=r"(af[mi][0]), "=r"(af[mi][1]), "=r"(af[mi][2]), "=r"(af[mi][3])
                             : "r"(addr));
            }
            uint32_t bq[2][4];
#pragma unroll
            for (int nf = 0; nf < 2; nf++) {
                uint32_t addr = smem_u32_(
                    bufB + (wn + (nf << 4) + ((lg >> 1) << 3) + lr) * 72 + (ks << 4) + ((lg & 1) << 3));
                asm volatile("ldmatrix.sync.aligned.m8n8.x4.shared.b16 {%0,%1,%2,%3}, [%4];"
                             : "=r"(bq[nf][0]), "=r"(bq[nf][1]), "=r"(bq[nf][2]), "=r"(bq[nf][3])
                             : "r"(addr));
            }
#pragma unroll
            for (int mi = 0; mi < 4; mi++)
#pragma unroll
                for (int ni = 0; ni < 4; ni++) {
                    const uint32_t b0 = bq[ni >> 1][(ni & 1) << 1];
                    const uint32_t b1 = bq[ni >> 1][((ni & 1) << 1) + 1];
                    asm volatile(
                        "mma.sync.aligned.m16n8k16.row.col.f32.bf16.bf16.f32 "
                        "{%0,%1,%2,%3}, {%4,%5,%6,%7}, {%8,%9}, {%0,%1,%2,%3};"
                        : "+f"(acc[mi][ni][0]), "+f"(acc[mi][ni][1]),
                          "+f"(acc[mi][ni][2]), "+f"(acc[mi][ni][3])
                        : "r"(af[mi][0]), "r"(af[mi][1]), "r"(af[mi][2]), "r"(af[mi][3]),
                          "r"(b0), "r"(b1));
                }
        }
        __syncthreads();
    }

    // epilogue: exp(acc + bias), store to EXTV-strided output, accumulate row sums
    const int er = lane >> 2;
    const int ec = (lane & 3) << 1;
#pragma unroll
    for (int mi = 0; mi < 4; mi++) {
        float rs0 = 0.f, rs1 = 0.f;
        size_t row0 = (size_t)(m0 + wm + (mi << 4) + er);
#pragma unroll
        for (int ni = 0; ni < 4; ni++) {
            int col = n0 + wn + (ni << 3) + ec;
            if (col < VV_) {   // col even, VV even -> col+1 < VV too
                float b0v = bias[col], b1v = bias[col + 1];
                float e0 = __expf(acc[mi][ni][0] + b0v);
                float e1 = __expf(acc[mi][ni][1] + b1v);
                float e2 = __expf(acc[mi][ni][2] + b0v);
                float e3 = __expf(acc[mi][ni][3] + b1v);
                *(float2*)&outE[row0 * EXTV_ + col] = make_float2(e0, e1);
                *(float2*)&outE[(row0 + 8) * EXTV_ + col] = make_float2(e2, e3);
                rs0 += e0 + e1;
                rs1 += e2 + e3;
            }
        }
        rs0 += __shfl_xor_sync(0xffffffffu, rs0, 1);
        rs0 += __shfl_xor_sync(0xffffffffu, rs0, 2);
        rs1 += __shfl_xor_sync(0xffffffffu, rs1, 1);
        rs1 += __shfl_xor_sync(0xffffffffu, rs1, 2);
        if ((lane & 3) == 0) {
            atomicAdd(&g_Z[row0], rs0);
            atomicAdd(&g_Z[row0 + 8], rs1);
        }
    }
}

// ---------------- single-pass register-tiled pooled attention ----------------
#define ATTN_SMEM ((128 * 65 + 64 * 128 + 16 * 128 + 128) * 4)
__global__ __launch_bounds__(256) void attn_pool2_k(const float* __restrict__ qk,
                                                    const float* __restrict__ enc) {
    extern __shared__ float sm[];
    float* Qh   = sm;
    float* KhT  = Qh + 128 * 65;
    float* part = KhT + 64 * 128;
    float* w    = part + 16 * 128;
    const int h = blockIdx.x, b = blockIdx.y;
    const int tid = threadIdx.x;
    const int tx = tid & 15, ty = tid >> 4;

    for (int i = tid; i < 2048; i += 256) {
        int r = i >> 4, c4 = (i & 15) << 2;
        float4 v = *(const float4*)(qk + ((size_t)(b * 128 + r)) * 1024 + h * 64 + c4);
        float* dst = Qh + r * 65 + c4;
        dst[0] = v.x; dst[1] = v.y; dst[2] = v.z; dst[3] = v.w;
        float4 u = *(const float4*)(qk + ((size_t)(b * 128 + r)) * 1024 + 512 + h * 64 + c4);
        KhT[(c4 + 0) * 128 + r] = u.x;
        KhT[(c4 + 1) * 128 + r] = u.y;
        KhT[(c4 + 2) * 128 + r] = u.z;
        KhT[(c4 + 3) * 128 + r] = u.w;
    }
    __syncthreads();

    float acc[8][8];
#pragma unroll
    for (int i = 0; i < 8; i++)
#pragma unroll
        for (int j = 0; j < 8; j++) acc[i][j] = 0.f;

    for (int k = 0; k < 64; k++) {
        float a[8], bb[8];
#pragma unroll
        for (int i = 0; i < 8; i++) a[i] = Qh[(ty + (i << 4)) * 65 + k];
#pragma unroll
        for (int j = 0; j < 8; j++) bb[j] = KhT[k * 128 + tx + (j << 4)];
#pragma unroll
        for (int i = 0; i < 8; i++)
#pragma unroll
            for (int j = 0; j < 8; j++) acc[i][j] = fmaf(a[i], bb[j], acc[i][j]);
    }

    float rs[8];
#pragma unroll
    for (int i = 0; i < 8; i++) {
        float s = 0.f;
#pragma unroll
        for (int j = 0; j < 8; j++) {
            float e = __expf(acc[i][j]);
            acc[i][j] = e;
            s += e;
        }
        rs[i] = s;
    }
#pragma unroll
    for (int m = 1; m < 16; m <<= 1)
#pragma unroll
        for (int i = 0; i < 8; i++) rs[i] += __shfl_xor_sync(0xffffffffu, rs[i], m);

    float cs[8];
#pragma unroll
    for (int j = 0; j < 8; j++) cs[j] = 0.f;
#pragma unroll
    for (int i = 0; i < 8; i++) {
        float zi = 1.f / rs[i];
#pragma unroll
        for (int j = 0; j < 8; j++) cs[j] = fmaf(acc[i][j], zi, cs[j]);
    }
#pragma unroll
    for (int j = 0; j < 8; j++) part[ty * 128 + tx + (j << 4)] = cs[j];
    __syncthreads();

    if (tid < 128) {
        float s = 0.f;
#pragma unroll
        for (int t2 = 0; t2 < 16; t2++) s += part[t2 * 128 + tid];
        w[tid] = s * (1.f / 128.f);
    }
    __syncthreads();

    float ea0 = 0.f, ea1 = 0.f;
    const float* encb = enc + (size_t)b * 128 * 512;
    for (int t = 0; t < 128; t++) {
        float wt = w[t];
        ea0 = fmaf(wt, encb[t * 512 + tid], ea0);
        ea1 = fmaf(wt, encb[t * 512 + tid + 256], ea1);
    }
    float* eo = g_e + ((size_t)b * 8 + h) * 512;
    eo[tid] = ea0;
    eo[tid + 256] = ea1;
}

// ---------------- weight prep kernels ----------------
__global__ void build_wgT_k(const float* __restrict__ Wih, const float* __restrict__ Whh) {
    int idx = blockIdx.x * 256 + threadIdx.x;
    if (idx >= 384 * 1024) return;
    int j = idx >> 10, r = idx & 1023;
    g_wgT[idx] = (j < 128) ? Wih[(size_t)r * 128 + j] : Whh[(size_t)r * 256 + (j - 128)];
}

__global__ void transpose_k(const float* __restrict__ in, float* __restrict__ out, int R, int C) {
    __shared__ float t[32][33];
    int c0 = blockIdx.x << 5, r0 = blockIdx.y << 5;
    int c = c0 + threadIdx.x;
    for (int i = threadIdx.y; i < 32; i += 8) {
        int r = r0 + i;
        if (r < R && c < C) t[i][threadIdx.x] = in[(size_t)r * C + c];
    }
    __syncthreads();
    int rr = r0 + threadIdx.x;
    for (int i = threadIdx.y; i < 32; i += 8) {
        int cc = c0 + i;
        if (cc < C && rr < R) out[(size_t)cc * R + rr] = t[threadIdx.x][i];
    }
}

// ---------------- concat builders ----------------
__global__ void cat1_k(const float* __restrict__ ct1, const float* __restrict__ embW,
                       const int* __restrict__ y) {
    int idx = blockIdx.x * 256 + threadIdx.x;
    if (idx >= 512 * 640) return;
    int b = idx / 640, j = idx - b * 640;
    g_cat1[idx] = (j < 512) ? ct1[(size_t)b * 512 + j]
                            : embW[(size_t)y[b] * 128 + (j - 512)];
}

__global__ void cat2_k(const float* __restrict__ h0) {
    int idx = blockIdx.x * 256 + threadIdx.x;
    if (idx >= 512 * 384) return;
    int b = idx / 384, j = idx - b * 384;
    g_cat2[idx] = (j < 128) ? g_x[b * 128 + j] : h0[(size_t)b * 256 + (j - 128)];
}

__global__ void cat3_k() {
    int idx = blockIdx.x * 256 + threadIdx.x;
    if (idx >= 512 * 768) return;
    int b = idx / 768, j = idx - b * 768;
    g_cat3[idx] = (j < 256) ? g_h[b * 256 + j] : g_ct[b * 512 + (j - 256)];
}

// ---------------- small dense ----------------
__global__ __launch_bounds__(256) void dense8_k(const float* __restrict__ X,
                                                const float* __restrict__ Wt,
                                                const float* __restrict__ b1,
                                                const float* __restrict__ b2,
                                                float* __restrict__ Y, int K, int N) {
    __shared__ float xs[8 * 768];
    const int tid = threadIdx.x;
    const int m0 = blockIdx.y << 3;
    const int col = (blockIdx.x << 8) + tid;
    for (int i = tid; i < (K << 3); i += 256) {
        int r = i / K, j = i - r * K;
        xs[i] = X[(size_t)(m0 + r) * K + j];
    }
    __syncthreads();
    if (col >= N) return;
    float acc[8];
#pragma unroll
    for (int r = 0; r < 8; r++) acc[r] = 0.f;
#pragma unroll 4
    for (int j = 0; j < K; j++) {
        float w = Wt[(size_t)j * N + col];
#pragma unroll
        for (int r = 0; r < 8; r++) acc[r] = fmaf(xs[r * K + j], w, acc[r]);
    }
    float bb = (b1 ? b1[col] : 0.f) + (b2 ? b2[col] : 0.f);
#pragma unroll
    for (int r = 0; r < 8; r++) Y[(size_t)(m0 + r) * N + col] = acc[r] + bb;
}

// ---------------- LSTM pointwise ----------------
__global__ void lstm_k(const float* __restrict__ c0, float* __restrict__ outH, float* __restrict__ outC) {
    int i = blockIdx.x * 256 + threadIdx.x;
    if (i >= 512 * 256) return;
    int b = i >> 8, u = i & 255;
    const float* g = &g_gates[b * 1024];
    float ig = sigmoidf_(g[u]);
    float fg = sigmoidf_(g[256 + u]);
    float gg = tanhf(g[512 + u]);
    float og = sigmoidf_(g[768 + u]);
    float cn = fg * c0[i] + ig * gg;
    float hn = og * tanhf(cn);
    g_h[i] = hn;
    g_c[i] = cn;
    if (outH) outH[i] = hn;
    if (outC) outC[i] = cn;
}

// ---------------- per-head Wv fold ----------------
__global__ __launch_bounds__(128) void wv_head_k() {
    __shared__ float es[8 * 2 * 512];
    const int tid = threadIdx.x;
    const int cx = blockIdx.x;
    const int b0 = blockIdx.y << 3;
    const int hbase = cx << 1;

    for (int i = tid; i < 8 * 2 * 512; i += 128) {
        int bb = i >> 10;
        int rem = i & 1023;
        int hh = rem >> 9;
        int j = rem & 511;
        es[i] = g_e[((size_t)(b0 + bb) * 8 + hbase + hh) * 512 + j];
    }
    __syncthreads();

    const int col = (cx << 7) + tid;
    const int hh = tid >> 6;
    float acc[8];
#pragma unroll
    for (int bb = 0; bb < 8; bb++) acc[bb] = 0.f;
    for (int j = 0; j < 512; j++) {
        float w0 = g_wvT[(size_t)j * 512 + col];
#pragma unroll
        for (int bb = 0; bb < 8; bb++)
            acc[bb] = fmaf(es[(bb << 10) + (hh << 9) + j], w0, acc[bb]);
    }
#pragma unroll
    for (int bb = 0; bb < 8; bb++)
        g_pooled[(size_t)(b0 + bb) * 512 + col] = acc[bb];
}

// ---------------- pointer gate ----------------
__global__ void pgen_k(const float* __restrict__ pgW, const float* __restrict__ pgb,
                       float* __restrict__ outPG) {
    int b = blockIdx.x;
    int tid = threadIdx.x;
    float s = 0.f;
    for (int j = tid; j < 1152; j += 128) {
        float v;
        if (j < 512)       v = g_ct[b * 512 + j];
        else if (j < 768)  v = g_h[b * 256 + (j - 512)];
        else if (j < 1024) v = g_c[b * 256 + (j - 768)];
        else               v = g_x[b * 128 + (j - 1024)];
        s += v * pgW[j];
    }
    __shared__ float red[128];
    red[tid] = s;
    __syncthreads();
    for (int off = 64; off; off >>= 1) {
        if (tid < off) red[tid] += red[tid + off];
        __syncthreads();
    }
    if (tid == 0) {
        float p = sigmoidf_(red[0] + pgb[0]);
        g_pgen[b] = p;
        if (outPG) outPG[b] = p;
    }
}

// ---------------- final distribution ----------------
__global__ void zeroZ_k() {
    int i = threadIdx.x;
    if (i < 512) g_Z[i] = 0.f;
}

__global__ void scale_k(float* __restrict__ out) {
    int i = blockIdx.x * 256 + threadIdx.x;
    if (i >= 512 * 12600) return;
    int b = i / 12600, r4 = i - b * 12600;
    float4* o = (float4*)out + (size_t)b * 12600 + r4;
    if (r4 < 12500) {
        float s = g_pgen[b] / g_Z[b];
        float4 v = *o;
        v.x *= s; v.y *= s; v.z *= s; v.w *= s;
        *o = v;
    } else {
        *o = make_float4(0.f, 0.f, 0.f, 0.f);
    }
}

__global__ void scatter_k(const int* __restrict__ ebev, float* __restrict__ out) {
    int idx = blockIdx.x * 256 + threadIdx.x;
    if (idx >= 512 * 512) return;
    int b = idx >> 9;
    float val = (1.f - g_pgen[b]) * g_ct[idx];
    atomicAdd(out + (size_t)b * EXTV_ + ebev[idx], val);
}

__global__ void copy_k(const float* __restrict__ src, float* __restrict__ dst, int n) {
    int i = blockIdx.x * 256 + threadIdx.x;
    if (i < n) dst[i] = src[i];
}

// ---------------- host-side symbol address helper ----------------
template <typename T>
static void* symaddr_(const T& sym) {
    void* p = nullptr;
    cudaGetSymbolAddress(&p, sym);
    return p;
}

// ---------------- host launcher ----------------
extern "C" void kernel_launch(void* const* d_in, const int* in_sizes, int n_in,
                              void* d_out, int out_size) {
    const int*   y    = (const int*)  d_in[0];
    const float* h0   = (const float*)d_in[1];
    const float* c0   = (const float*)d_in[2];
    const float* enc  = (const float*)d_in[3];
    const float* ct1  = (const float*)d_in[6];
    const int*   ebev = (const int*)  d_in[8];
    const float* cov  = (const float*)d_in[9];

    int wb = 10;
    for (int i = 10; i < n_in; i++) {
        if (in_sizes[i] == 6400000) { wb = i; break; }
    }
    const float* embW = (const float*)d_in[wb + 0];
    const float* xcW  = (const float*)d_in[wb + 1];
    const float* xcb  = (const float*)d_in[wb + 2];
    const float* Wih  = (const float*)d_in[wb + 3];
    const float* Whh  = (const float*)d_in[wb + 4];
    const float* bih  = (const float*)d_in[wb + 5];
    const float* bhh  = (const float*)d_in[wb + 6];
    const float* Wq   = (const float*)d_in[wb + 7];
    const float* Wk   = (const float*)d_in[wb + 8];
    const float* Wv   = (const float*)d_in[wb + 9];
    const float* Wo   = (const float*)d_in[wb + 10];
    const float* pgW  = (const float*)d_in[wb + 11];
    const float* pgb  = (const float*)d_in[wb + 12];
    const float* o1W  = (const float*)d_in[wb + 13];
    const float* o1b  = (const float*)d_in[wb + 14];
    const float* o2W  = (const float*)d_in[wb + 15];
    const float* o2b  = (const float*)d_in[wb + 16];
    float* out = (float*)d_out;
    const bool full = (out_size >= OUT_FULL);

    float* p_qk   = (float*)symaddr_(g_qk);
    __nv_bfloat16* p_Ab = (__nv_bfloat16*)symaddr_(g_Ab);
    __nv_bfloat16* p_Bb = (__nv_bfloat16*)symaddr_(g_Bb);
    __nv_bfloat16* p_o2b = (__nv_bfloat16*)symaddr_(g_o2b);
    __nv_bfloat16* p_out1b = (__nv_bfloat16*)symaddr_(g_out1b);
    float* p_wgT  = (float*)symaddr_(g_wgT);
    float* p_xcWT = (float*)symaddr_(g_xcWT);
    float* p_o1WT = (float*)symaddr_(g_o1WT);
    float* p_wvT  = (float*)symaddr_(g_wvT);
    float* p_woT  = (float*)symaddr_(g_woT);
    float* p_cat1 = (float*)symaddr_(g_cat1);
    float* p_x    = (float*)symaddr_(g_x);
    float* p_cat2 = (float*)symaddr_(g_cat2);
    float* p_gates= (float*)symaddr_(g_gates);
    float* p_pool = (float*)symaddr_(g_pooled);
    float* p_ct   = (float*)symaddr_(g_ct);
    float* p_cat3 = (float*)symaddr_(g_cat3);
    float* p_out1 = (float*)symaddr_(g_out1);

    cudaFuncSetAttribute(attn_pool2_k, cudaFuncAttributeMaxDynamicSharedMemorySize, ATTN_SMEM);
    cudaFuncSetAttribute(qk_mma_k, cudaFuncAttributeMaxDynamicSharedMemorySize, QK_SMEM);
    cudaFuncSetAttribute(logits_mma_k, cudaFuncAttributeMaxDynamicSharedMemorySize, QK_SMEM);

    // launches 1-3, then attn_pool2_k at slot 4 (the launch ncu profiles)
    buildAb_k<<<131072, 256>>>(enc, p_Ab);
    buildBb_k<<<2048, 256>>>(Wq, Wk, p_Bb);
    qk_mma_k<<<dim3(16, 512), 128, QK_SMEM>>>(p_Ab, p_Bb, p_qk);
    attn_pool2_k<<<dim3(8, 512), 256, ATTN_SMEM>>>(p_qk, enc);

    // weight prep
    build_wgT_k<<<1536, 256>>>(Wih, Whh);
    buildO2b_k<<<(VPAD_ * 256 + 255) / 256, 256>>>(o2W, p_o2b);
    transpose_k<<<dim3(20, 4),   dim3(32, 8)>>>(xcW, p_xcWT, 128, 640);
    transpose_k<<<dim3(24, 8),   dim3(32, 8)>>>(o1W, p_o1WT, 256, 768);
    transpose_k<<<dim3(16, 16),  dim3(32, 8)>>>(Wv, p_wvT, 512, 512);
    transpose_k<<<dim3(16, 16),  dim3(32, 8)>>>(Wo, p_woT, 512, 512);

    // embedding + x projection
    cat1_k<<<1280, 256>>>(ct1, embW, y);
    dense8_k<<<dim3(1, 64), 256>>>(p_cat1, p_xcWT, xcb, nullptr, p_x, 640, 128);

    // LSTM
    cat2_k<<<768, 256>>>(h0);
    dense8_k<<<dim3(4, 64), 256>>>(p_cat2, p_wgT, bih, bhh, p_gates, 384, 1024);
    lstm_k<<<512, 256>>>(c0, full ? out + OFF_H : nullptr, full ? out + OFF_C : nullptr);

    // attention tail: per-head Wv fold + Wo
    wv_head_k<<<dim3(4, 64), 128>>>();
    dense8_k<<<dim3(2, 64), 256>>>(p_pool, p_woT, nullptr, nullptr, p_ct, 512, 512);

    // pointer gate
    pgen_k<<<512, 128>>>(pgW, pgb, full ? out + OFF_PG : nullptr);

    // vocab head (bf16 HMMA logits)
    cat3_k<<<1536, 256>>>();
    dense8_k<<<dim3(1, 64), 256>>>(p_cat3, p_o1WT, o1b, nullptr, p_out1, 768, 256);
    build_out1b_k<<<512, 256>>>();
    zeroZ_k<<<1, 512>>>();
    logits_mma_k<<<dim3(782, 4), 128, QK_SMEM>>>(p_out1b, p_o2b, o2b, out);

    // final distribution
    scale_k<<<25200, 256>>>(out);
    scatter_k<<<1024, 256>>>(ebev, out);

    if (full) {
        copy_k<<<1024, 256>>>(p_ct, out + OFF_CT1, 262144);
        copy_k<<<1024, 256>>>(p_ct, out + OFF_CT2, 262144);
        copy_k<<<256, 256>>>(cov, out + OFF_COV, 65536);
    }
}

// round 15
// speedup vs baseline: 2.5995x; 1.0257x over previous
#include <cuda_runtime.h>
#include <cuda_bf16.h>
#include <math.h>
#include <stdint.h>

// ---------------- problem constants ----------------
#define VV_  50000
#define EXTV_ 50400
#define VPAD_ 50048   // 64-aligned padded vocab

// output offsets (flattened tuple order)
#define OFF_FD  0
#define OFF_H   25804800
#define OFF_C   25935872
#define OFF_CT1 26066944
#define OFF_CT2 26329088
#define OFF_PG  26591232
#define OFF_COV 26591744
#define OUT_FULL 26657280

// ---------------- device scratch (no cudaMalloc allowed) ----------------
__device__ __nv_bfloat16 g_qkb[(size_t)65536 * 1024]; // Q | K per enc position (bf16)
__device__ __nv_bfloat16 g_Ab[(size_t)65536 * 512];   // bf16(enc)
__device__ __nv_bfloat16 g_Bb[1024 * 512];            // bf16([Wq;Wk]), K half pre-scaled by 1/8
__device__ __nv_bfloat16 g_o2b[(size_t)VPAD_ * 256];  // bf16(o2W), zero-padded rows
__device__ __nv_bfloat16 g_out1b[512 * 256];          // bf16(out1)
__device__ float g_wgT[384 * 1024];
__device__ float g_xcWT[640 * 128];
__device__ float g_o1WT[768 * 256];
__device__ float g_wvT[512 * 512];
__device__ float g_woT[512 * 512];
__device__ float g_cat1[512 * 640];
__device__ float g_x[512 * 128];
__device__ float g_cat2[512 * 384];
__device__ float g_gates[512 * 1024];
__device__ float g_h[512 * 256];
__device__ float g_c[512 * 256];
__device__ float g_e[512 * 8 * 512];
__device__ float g_pooled[512 * 512];
__device__ float g_ct[512 * 512];
__device__ float g_cat3[512 * 768];
__device__ float g_out1[512 * 256];
__device__ float g_pgen[512];
__device__ float g_Z[512];

__device__ __forceinline__ float sigmoidf_(float x) { return 1.0f / (1.0f + __expf(-x)); }

__device__ __forceinline__ uint32_t smem_u32_(const void* p) {
    uint32_t a;
    asm("{ .reg .u64 t; cvta.to.shared.u64 t, %1; cvt.u32.u64 %0, t; }" : "=r"(a) : "l"(p));
    return a;
}

__device__ __forceinline__ void cp_async16_(uint32_t dst, const void* src) {
    asm volatile("cp.async.cg.shared.global [%0], [%1], 16;" :: "r"(dst), "l"(src));
}

__device__ __forceinline__ uint32_t packbf2_(float x, float y) {
    __nv_bfloat162 h = __floats2bfloat162_rn(x, y);
    return *(uint32_t*)&h;
}

// ---------------- bf16 conversion prep ----------------
__global__ void buildAb_k(const float* __restrict__ enc, __nv_bfloat16* __restrict__ A) {
    int i = blockIdx.x * 256 + threadIdx.x;
    if (i >= 65536 * 512) return;
    A[i] = __float2bfloat16(enc[i]);
}

// K rows (n >= 512) pre-scaled by 0.125 so attention skips the softmax scale
__global__ void buildBb_k(const float* __restrict__ Wq, const float* __restrict__ Wk,
                          __nv_bfloat16* __restrict__ B) {
    int i = blockIdx.x * 256 + threadIdx.x;
    if (i >= 1024 * 512) return;
    int n = i >> 9, k = i & 511;
    float v = (n < 512) ? Wq[(size_t)n * 512 + k]
                        : Wk[(size_t)(n - 512) * 512 + k] * 0.125f;
    B[i] = __float2bfloat16(v);
}

__global__ void buildO2b_k(const float* __restrict__ o2W, __nv_bfloat16* __restrict__ B) {
    int i = blockIdx.x * 256 + threadIdx.x;
    if (i >= VPAD_ * 256) return;
    int r = i >> 8;
    B[i] = (r < VV_) ? __float2bfloat16(o2W[(size_t)r * 256 + (i & 255)]) : __nv_bfloat16(0.f);
}

__global__ void build_out1b_k() {
    int i = blockIdx.x * 256 + threadIdx.x;
    if (i >= 512 * 256) return;
    g_out1b[i] = __float2bfloat16(g_out1[i]);
}

// ---------------- bf16 HMMA GEMM, 2-stage cp.async, 4-warp / 64x32 warp tile ----------------
// Cb[65536,1024] (bf16) = A[.,512] @ B[.,512]^T  (K=512 -> 8 k-tiles of 64)
#define QK_SMEM ((2 * 128 * 72 + 2 * 64 * 72) * 2)
__global__ __launch_bounds__(128) void qk_mma_k(const __nv_bfloat16* __restrict__ A,
                                                const __nv_bfloat16* __restrict__ B,
                                                __nv_bfloat16* __restrict__ Cb) {
    extern __shared__ __nv_bfloat16 smem_bf[];
    const int tid = threadIdx.x;
    const int wid = tid >> 5, lane = tid & 31;
    const int wm = (wid & 1) << 6;
    const int wn = (wid >> 1) << 5;
    const int m0 = blockIdx.y << 7;
    const int n0 = blockIdx.x << 6;
    const int lr = lane & 7;
    const int lg = lane >> 3;

    const int rA = tid >> 3;
    const int c8 = (tid & 7) << 3;

    float acc[4][4][4];
#pragma unroll
    for (int mi = 0; mi < 4; mi++)
#pragma unroll
        for (int ni = 0; ni < 4; ni++)
#pragma unroll
            for (int r = 0; r < 4; r++) acc[mi][ni][r] = 0.f;

#pragma unroll
    for (int i = 0; i < 8; i++) {
        int r = rA + (i << 4);
        cp_async16_(smem_u32_(&smem_bf[r * 72 + c8]), A + (size_t)(m0 + r) * 512 + c8);
    }
#pragma unroll
    for (int i = 0; i < 4; i++) {
        int r = rA + (i << 4);
        cp_async16_(smem_u32_(&smem_bf[18432 + r * 72 + c8]), B + (size_t)(n0 + r) * 512 + c8);
    }
    asm volatile("cp.async.commit_group;" ::: "memory");

    for (int kt = 0; kt < 8; kt++) {
        const int buf = kt & 1;
        if (kt < 7) {
            const int nb = (kt + 1) & 1;
            const int kof = (kt + 1) << 6;
#pragma unroll
            for (int i = 0; i < 8; i++) {
                int r = rA + (i << 4);
                cp_async16_(smem_u32_(&smem_bf[nb * 9216 + r * 72 + c8]),
                            A + (size_t)(m0 + r) * 512 + kof + c8);
            }
#pragma unroll
            for (int i = 0; i < 4; i++) {
                int r = rA + (i << 4);
                cp_async16_(smem_u32_(&smem_bf[18432 + nb * 4608 + r * 72 + c8]),
                            B + (size_t)(n0 + r) * 512 + kof + c8);
            }
            asm volatile("cp.async.commit_group;" ::: "memory");
            asm volatile("cp.async.wait_group 1;" ::: "memory");
        } else {
            asm volatile("cp.async.wait_group 0;" ::: "memory");
        }
        __syncthreads();

        const __nv_bfloat16* bufA = smem_bf + buf * 9216;
        const __nv_bfloat16* bufB = smem_bf + 18432 + buf * 4608;
#pragma unroll
        for (int ks = 0; ks < 4; ks++) {
            uint32_t af[4][4];
#pragma unroll
            for (int mi = 0; mi < 4; mi++) {
                uint32_t addr = smem_u32_(
                    bufA + (wm + (mi << 4) + lr + ((lg & 1) << 3)) * 72 + (ks << 4) + ((lg >> 1) << 3));
                asm volatile("ldmatrix.sync.aligned.m8n8.x4.shared.b16 {%0,%1,%2,%3}, [%4];"
                             : "=r"(af[mi][0]), "=r"(af[mi][1]), "=r"(af[mi][2]), "=r"(af[mi][3])
                             : "r"(addr));
            }
            uint32_t bq[2][4];
#pragma unroll
            for (int nf = 0; nf < 2; nf++) {
                uint32_t addr = smem_u32_(
                    bufB + (wn + (nf << 4) + ((lg >> 1) << 3) + lr) * 72 + (ks << 4) + ((lg & 1) << 3));
                asm volatile("ldmatrix.sync.aligned.m8n8.x4.shared.b16 {%0,%1,%2,%3}, [%4];"
                             : "=r"(bq[nf][0]), "=r"(bq[nf][1]), "=r"(bq[nf][2]), "=r"(bq[nf][3])
                             : "r"(addr));
            }
#pragma unroll
            for (int mi = 0; mi < 4; mi++)
#pragma unroll
                for (int ni = 0; ni < 4; ni++) {
                    const uint32_t b0 = bq[ni >> 1][(ni & 1) << 1];
                    const uint32_t b1 = bq[ni >> 1][((ni & 1) << 1) + 1];
                    asm volatile(
                        "mma.sync.aligned.m16n8k16.row.col.f32.bf16.bf16.f32 "
                        "{%0,%1,%2,%3}, {%4,%5,%6,%7}, {%8,%9}, {%0,%1,%2,%3};"
                        : "+f"(acc[mi][ni][0]), "+f"(acc[mi][ni][1]),
                          "+f"(acc[mi][ni][2]), "+f"(acc[mi][ni][3])
                        : "r"(af[mi][0]), "r"(af[mi][1]), "r"(af[mi][2]), "r"(af[mi][3]),
                          "r"(b0), "r"(b1));
                }
        }
        __syncthreads();
    }

    const int er = lane >> 2;
    const int ec = (lane & 3) << 1;
#pragma unroll
    for (int mi = 0; mi < 4; mi++) {
#pragma unroll
        for (int ni = 0; ni < 4; ni++) {
            size_t row = (size_t)(m0 + wm + (mi << 4) + er);
            int col = n0 + wn + (ni << 3) + ec;
            *(uint32_t*)&Cb[row * 1024 + col] = packbf2_(acc[mi][ni][0], acc[mi][ni][1]);
            *(uint32_t*)&Cb[(row + 8) * 1024 + col] = packbf2_(acc[mi][ni][2], acc[mi][ni][3]);
        }
    }
}

// ---------------- bf16 HMMA logits GEMM fused with exp + bias + row-sum ----------------
__global__ __launch_bounds__(128) void logits_mma_k(const __nv_bfloat16* __restrict__ A,
                                                    const __nv_bfloat16* __restrict__ B,
                                                    const float* __restrict__ bias,
                                                    float* __restrict__ outE) {
    extern __shared__ __nv_bfloat16 smem_bf[];
    const int tid = threadIdx.x;
    const int wid = tid >> 5, lane = tid & 31;
    const int wm = (wid & 1) << 6;
    const int wn = (wid >> 1) << 5;
    const int m0 = blockIdx.y << 7;
    const int n0 = blockIdx.x << 6;
    const int lr = lane & 7;
    const int lg = lane >> 3;

    const int rA = tid >> 3;
    const int c8 = (tid & 7) << 3;

    float acc[4][4][4];
#pragma unroll
    for (int mi = 0; mi < 4; mi++)
#pragma unroll
        for (int ni = 0; ni < 4; ni++)
#pragma unroll
            for (int r = 0; r < 4; r++) acc[mi][ni][r] = 0.f;

#pragma unroll
    for (int i = 0; i < 8; i++) {
        int r = rA + (i << 4);
        cp_async16_(smem_u32_(&smem_bf[r * 72 + c8]), A + (size_t)(m0 + r) * 256 + c8);
    }
#pragma unroll
    for (int i = 0; i < 4; i++) {
        int r = rA + (i << 4);
        cp_async16_(smem_u32_(&smem_bf[18432 + r * 72 + c8]), B + (size_t)(n0 + r) * 256 + c8);
    }
    asm volatile("cp.async.commit_group;" ::: "memory");

    for (int kt = 0; kt < 4; kt++) {
        const int buf = kt & 1;
        if (kt < 3) {
            const int nb = (kt + 1) & 1;
            const int kof = (kt + 1) << 6;
#pragma unroll
            for (int i = 0; i < 8; i++) {
                int r = rA + (i << 4);
                cp_async16_(smem_u32_(&smem_bf[nb * 9216 + r * 72 + c8]),
                            A + (size_t)(m0 + r) * 256 + kof + c8);
            }
#pragma unroll
            for (int i = 0; i < 4; i++) {
                int r = rA + (i << 4);
                cp_async16_(smem_u32_(&smem_bf[18432 + nb * 4608 + r * 72 + c8]),
                            B + (size_t)(n0 + r) * 256 + kof + c8);
            }
            asm volatile("cp.async.commit_group;" ::: "memory");
            asm volatile("cp.async.wait_group 1;" ::: "memory");
        } else {
            asm volatile("cp.async.wait_group 0;" ::: "memory");
        }
        __syncthreads();

        const __nv_bfloat16* bufA = smem_bf + buf * 9216;
        const __nv_bfloat16* bufB = smem_bf + 18432 + buf * 4608;
#pragma unroll
        for (int ks = 0; ks < 4; ks++) {
            uint32_t af[4][4];
#pragma unroll
            for (int mi = 0; mi < 4; mi++) {
                uint32_t addr = smem_u32_(
                    bufA + (wm + (mi << 4) + lr + ((lg & 1) << 3)) * 72 + (ks << 4) + ((lg >> 1) << 3));
                asm volatile("ldmatrix.sync.aligned.m8n8.x4.shared.b16 {%0,%1,%2,%3}, [%4];"
                             : "=r"(af[mi][0]), "=r"(af[mi][1]), "=r"(af[mi][2]), "=r"(af[mi][3])
                             : "r"(addr));
            }
            uint32_t bq[2][4];
#pragma unroll
            for (int nf = 0; nf < 2; nf++) {
                uint32_t addr = smem_u32_(
                    bufB + (wn + (nf << 4) + ((lg >> 1) << 3) + lr) * 72 + (ks << 4) + ((lg & 1) << 3));
                asm volatile("ldmatrix.sync.aligned.m8n8.x4.shared.b16 {%0,%1,%2,%3}, [%4];"
                             : "=r"(bq[nf][0]), "=r"(bq[nf][1]), "=r"(bq[nf][2]), "=r"(bq[nf][3])
                             : "r"(addr));
            }
#pragma unroll
            for (int mi = 0; mi < 4; mi++)
#pragma unroll
                for (int ni = 0; ni < 4; ni++) {
                    const uint32_t b0 = bq[ni >> 1][(ni & 1) << 1];
                    const uint32_t b1 = bq[ni >> 1][((ni & 1) << 1) + 1];
                    asm volatile(
                        "mma.sync.aligned.m16n8k16.row.col.f32.bf16.bf16.f32 "
                        "{%0,%1,%2,%3}, {%4,%5,%6,%7}, {%8,%9}, {%0,%1,%2,%3};"
                        : "+f"(acc[mi][ni][0]), "+f"(acc[mi][ni][1]),
                          "+f"(acc[mi][ni][2]), "+f"(acc[mi][ni][3])
                        : "r"(af[mi][0]), "r"(af[mi][1]), "r"(af[mi][2]), "r"(af[mi][3]),
                          "r"(b0), "r"(b1));
                }
        }
        __syncthreads();
    }

    const int er = lane >> 2;
    const int ec = (lane & 3) << 1;
#pragma unroll
    for (int mi = 0; mi < 4; mi++) {
        float rs0 = 0.f, rs1 = 0.f;
        size_t row0 = (size_t)(m0 + wm + (mi << 4) + er);
#pragma unroll
        for (int ni = 0; ni < 4; ni++) {
            int col = n0 + wn + (ni << 3) + ec;
            if (col < VV_) {
                float b0v = bias[col], b1v = bias[col + 1];
                float e0 = __expf(acc[mi][ni][0] + b0v);
                float e1 = __expf(acc[mi][ni][1] + b1v);
                float e2 = __expf(acc[mi][ni][2] + b0v);
                float e3 = __expf(acc[mi][ni][3] + b1v);
                *(float2*)&outE[row0 * EXTV_ + col] = make_float2(e0, e1);
                *(float2*)&outE[(row0 + 8) * EXTV_ + col] = make_float2(e2, e3);
                rs0 += e0 + e1;
                rs1 += e2 + e3;
            }
        }
        rs0 += __shfl_xor_sync(0xffffffffu, rs0, 1);
        rs0 += __shfl_xor_sync(0xffffffffu, rs0, 2);
        rs1 += __shfl_xor_sync(0xffffffffu, rs1, 1);
        rs1 += __shfl_xor_sync(0xffffffffu, rs1, 2);
        if ((lane & 3) == 0) {
            atomicAdd(&g_Z[row0], rs0);
            atomicAdd(&g_Z[row0 + 8], rs1);
        }
    }
}

// ---------------- single-pass register-tiled pooled attention (bf16 qk input) ----------------
#define ATTN_SMEM ((128 * 65 + 64 * 128 + 16 * 128 + 128) * 4)
__global__ __launch_bounds__(256) void attn_pool2_k(const __nv_bfloat16* __restrict__ qkb,
                                                    const float* __restrict__ enc) {
    extern __shared__ float sm[];
    float* Qh   = sm;
    float* KhT  = Qh + 128 * 65;
    float* part = KhT + 64 * 128;
    float* w    = part + 16 * 128;
    const int h = blockIdx.x, b = blockIdx.y;
    const int tid = threadIdx.x;
    const int tx = tid & 15, ty = tid >> 4;

    for (int i = tid; i < 2048; i += 256) {
        int r = i >> 4, c4 = (i & 15) << 2;
        const __nv_bfloat162* q2 =
            (const __nv_bfloat162*)(qkb + ((size_t)(b * 128 + r)) * 1024 + h * 64 + c4);
        __nv_bfloat162 v0 = q2[0], v1 = q2[1];
        float* dst = Qh + r * 65 + c4;
        dst[0] = __bfloat162float(v0.x);
        dst[1] = __bfloat162float(v0.y);
        dst[2] = __bfloat162float(v1.x);
        dst[3] = __bfloat162float(v1.y);
        const __nv_bfloat162* k2 =
            (const __nv_bfloat162*)(qkb + ((size_t)(b * 128 + r)) * 1024 + 512 + h * 64 + c4);
        __nv_bfloat162 u0 = k2[0], u1 = k2[1];
        KhT[(c4 + 0) * 128 + r] = __bfloat162float(u0.x);
        KhT[(c4 + 1) * 128 + r] = __bfloat162float(u0.y);
        KhT[(c4 + 2) * 128 + r] = __bfloat162float(u1.x);
        KhT[(c4 + 3) * 128 + r] = __bfloat162float(u1.y);
    }
    __syncthreads();

    float acc[8][8];
#pragma unroll
    for (int i = 0; i < 8; i++)
#pragma unroll
        for (int j = 0; j < 8; j++) acc[i][j] = 0.f;

    // software-pipelined k-loop (unroll-2, explicit prefetch)
    float a0[8], b0v[8], a1[8], b1v[8];
#pragma unroll
    for (int i = 0; i < 8; i++) {
        a0[i] = Qh[(ty + (i << 4)) * 65];
        b0v[i] = KhT[tx + (i << 4)];
    }
    for (int k = 0; k < 64; k += 2) {
#pragma unroll
        for (int i = 0; i < 8; i++) {
            a1[i] = Qh[(ty + (i << 4)) * 65 + k + 1];
            b1v[i] = KhT[(k + 1) * 128 + tx + (i << 4)];
        }
#pragma unroll
        for (int i = 0; i < 8; i++)
#pragma unroll
            for (int j = 0; j < 8; j++) acc[i][j] = fmaf(a0[i], b0v[j], acc[i][j]);
        if (k + 2 < 64) {
#pragma unroll
            for (int i = 0; i < 8; i++) {
                a0[i] = Qh[(ty + (i << 4)) * 65 + k + 2];
                b0v[i] = KhT[(k + 2) * 128 + tx + (i << 4)];
            }
        }
#pragma unroll
        for (int i = 0; i < 8; i++)
#pragma unroll
            for (int j = 0; j < 8; j++) acc[i][j] = fmaf(a1[i], b1v[j], acc[i][j]);
    }

    // K was pre-scaled by 1/8 -> scores already scaled
    float rs[8];
#pragma unroll
    for (int i = 0; i < 8; i++) {
        float s = 0.f;
#pragma unroll
        for (int j = 0; j < 8; j++) {
            float e = __expf(acc[i][j]);
            acc[i][j] = e;
            s += e;
        }
        rs[i] = s;
    }
#pragma unroll
    for (int m = 1; m < 16; m <<= 1)
#pragma unroll
        for (int i = 0; i < 8; i++) rs[i] += __shfl_xor_sync(0xffffffffu, rs[i], m);

    float cs[8];
#pragma unroll
    for (int j = 0; j < 8; j++) cs[j] = 0.f;
#pragma unroll
    for (int i = 0; i < 8; i++) {
        float zi = 1.f / rs[i];
#pragma unroll
        for (int j = 0; j < 8; j++) cs[j] = fmaf(acc[i][j], zi, cs[j]);
    }
#pragma unroll
    for (int j = 0; j < 8; j++) part[ty * 128 + tx + (j << 4)] = cs[j];
    __syncthreads();

    if (tid < 128) {
        float s = 0.f;
#pragma unroll
        for (int t2 = 0; t2 < 16; t2++) s += part[t2 * 128 + tid];
        w[tid] = s * (1.f / 128.f);
    }
    __syncthreads();

    float ea0 = 0.f, ea1 = 0.f;
    const float* encb = enc + (size_t)b * 128 * 512;
    for (int t = 0; t < 128; t++) {
        float wt = w[t];
        ea0 = fmaf(wt, encb[t * 512 + tid], ea0);
        ea1 = fmaf(wt, encb[t * 512 + tid + 256], ea1);
    }
    float* eo = g_e + ((size_t)b * 8 + h) * 512;
    eo[tid] = ea0;
    eo[tid + 256] = ea1;
}

// ---------------- weight prep kernels ----------------
__global__ void build_wgT_k(const float* __restrict__ Wih, const float* __restrict__ Whh) {
    int idx = blockIdx.x * 256 + threadIdx.x;
    if (idx >= 384 * 1024) return;
    int j = idx >> 10, r = idx & 1023;
    g_wgT[idx] = (j < 128) ? Wih[(size_t)r * 128 + j] : Whh[(size_t)r * 256 + (j - 128)];
}

__global__ void transpose_k(const float* __restrict__ in, float* __restrict__ out, int R, int C) {
    __shared__ float t[32][33];
    int c0 = blockIdx.x << 5, r0 = blockIdx.y << 5;
    int c = c0 + threadIdx.x;
    for (int i = threadIdx.y; i < 32; i += 8) {
        int r = r0 + i;
        if (r < R && c < C) t[i][threadIdx.x] = in[(size_t)r * C + c];
    }
    __syncthreads();
    int rr = r0 + threadIdx.x;
    for (int i = threadIdx.y; i < 32; i += 8) {
        int cc = c0 + i;
        if (cc < C && rr < R) out[(size_t)cc * R + rr] = t[threadIdx.x][i];
    }
}

// ---------------- concat builders ----------------
__global__ void cat1_k(const float* __restrict__ ct1, const float* __restrict__ embW,
                       const int* __restrict__ y) {
    int idx = blockIdx.x * 256 + threadIdx.x;
    if (idx >= 512 * 640) return;
    int b = idx / 640, j = idx - b * 640;
    g_cat1[idx] = (j < 512) ? ct1[(size_t)b * 512 + j]
                            : embW[(size_t)y[b] * 128 + (j - 512)];
}

__global__ void cat2_k(const float* __restrict__ h0) {
    int idx = blockIdx.x * 256 + threadIdx.x;
    if (idx >= 512 * 384) return;
    int b = idx / 384, j = idx - b * 384;
    g_cat2[idx] = (j < 128) ? g_x[b * 128 + j] : h0[(size_t)b * 256 + (j - 128)];
}

__global__ void cat3_k() {
    int idx = blockIdx.x * 256 + threadIdx.x;
    if (idx >= 512 * 768) return;
    int b = idx / 768, j = idx - b * 768;
    g_cat3[idx] = (j < 256) ? g_h[b * 256 + j] : g_ct[b * 512 + (j - 256)];
}

// ---------------- small dense ----------------
__global__ __launch_bounds__(256) void dense8_k(const float* __restrict__ X,
                                                const float* __restrict__ Wt,
                                                const float* __restrict__ b1,
                                                const float* __restrict__ b2,
                                                float* __restrict__ Y, int K, int N) {
    __shared__ float xs[8 * 768];
    const int tid = threadIdx.x;
    const int m0 = blockIdx.y << 3;
    const int col = (blockIdx.x << 8) + tid;
    for (int i = tid; i < (K << 3); i += 256) {
        int r = i / K, j = i - r * K;
        xs[i] = X[(size_t)(m0 + r) * K + j];
    }
    __syncthreads();
    if (col >= N) return;
    float acc[8];
#pragma unroll
    for (int r = 0; r < 8; r++) acc[r] = 0.f;
#pragma unroll 4
    for (int j = 0; j < K; j++) {
        float w = Wt[(size_t)j * N + col];
#pragma unroll
        for (int r = 0; r < 8; r++) acc[r] = fmaf(xs[r * K + j], w, acc[r]);
    }
    float bb = (b1 ? b1[col] : 0.f) + (b2 ? b2[col] : 0.f);
#pragma unroll
    for (int r = 0; r < 8; r++) Y[(size_t)(m0 + r) * N + col] = acc[r] + bb;
}

// ---------------- LSTM pointwise ----------------
__global__ void lstm_k(const float* __restrict__ c0, float* __restrict__ outH, float* __restrict__ outC) {
    int i = blockIdx.x * 256 + threadIdx.x;
    if (i >= 512 * 256) return;
    int b = i >> 8, u = i & 255;
    const float* g = &g_gates[b * 1024];
    float ig = sigmoidf_(g[u]);
    float fg = sigmoidf_(g[256 + u]);
    float gg = tanhf(g[512 + u]);
    float og = sigmoidf_(g[768 + u]);
    float cn = fg * c0[i] + ig * gg;
    float hn = og * tanhf(cn);
    g_h[i] = hn;
    g_c[i] = cn;
    if (outH) outH[i] = hn;
    if (outC) outC[i] = cn;
}

// ---------------- per-head Wv fold ----------------
__global__ __launch_bounds__(128) void wv_head_k() {
    __shared__ float es[8 * 2 * 512];
    const int tid = threadIdx.x;
    const int cx = blockIdx.x;
    const int b0 = blockIdx.y << 3;
    const int hbase = cx << 1;

    for (int i = tid; i < 8 * 2 * 512; i += 128) {
        int bb = i >> 10;
        int rem = i & 1023;
        int hh = rem >> 9;
        int j = rem & 511;
        es[i] = g_e[((size_t)(b0 + bb) * 8 + hbase + hh) * 512 + j];
    }
    __syncthreads();

    const int col = (cx << 7) + tid;
    const int hh = tid >> 6;
    float acc[8];
#pragma unroll
    for (int bb = 0; bb < 8; bb++) acc[bb] = 0.f;
    for (int j = 0; j < 512; j++) {
        float w0 = g_wvT[(size_t)j * 512 + col];
#pragma unroll
        for (int bb = 0; bb < 8; bb++)
            acc[bb] = fmaf(es[(bb << 10) + (hh << 9) + j], w0, acc[bb]);
    }
#pragma unroll
    for (int bb = 0; bb < 8; bb++)
        g_pooled[(size_t)(b0 + bb) * 512 + col] = acc[bb];
}

// ---------------- pointer gate ----------------
__global__ void pgen_k(const float* __restrict__ pgW, const float* __restrict__ pgb,
                       float* __restrict__ outPG) {
    int b = blockIdx.x;
    int tid = threadIdx.x;
    float s = 0.f;
    for (int j = tid; j < 1152; j += 128) {
        float v;
        if (j < 512)       v = g_ct[b * 512 + j];
        else if (j < 768)  v = g_h[b * 256 + (j - 512)];
        else if (j < 1024) v = g_c[b * 256 + (j - 768)];
        else               v = g_x[b * 128 + (j - 1024)];
        s += v * pgW[j];
    }
    __shared__ float red[128];
    red[tid] = s;
    __syncthreads();
    for (int off = 64; off; off >>= 1) {
        if (tid < off) red[tid] += red[tid + off];
        __syncthreads();
    }
    if (tid == 0) {
        float p = sigmoidf_(red[0] + pgb[0]);
        g_pgen[b] = p;
        if (outPG) outPG[b] = p;
    }
}

// ---------------- final distribution ----------------
__global__ void zeroZ_k() {
    int i = threadIdx.x;
    if (i < 512) g_Z[i] = 0.f;
}

__global__ void scale_k(float* __restrict__ out) {
    int i = blockIdx.x * 256 + threadIdx.x;
    if (i >= 512 * 12600) return;
    int b = i / 12600, r4 = i - b * 12600;
    float4* o = (float4*)out + (size_t)b * 12600 + r4;
    if (r4 < 12500) {
        float s = g_pgen[b] / g_Z[b];
        float4 v = *o;
        v.x *= s; v.y *= s; v.z *= s; v.w *= s;
        *o = v;
    } else {
        *o = make_float4(0.f, 0.f, 0.f, 0.f);
    }
}

__global__ void scatter_k(const int* __restrict__ ebev, float* __restrict__ out) {
    int idx = blockIdx.x * 256 + threadIdx.x;
    if (idx >= 512 * 512) return;
    int b = idx >> 9;
    float val = (1.f - g_pgen[b]) * g_ct[idx];
    atomicAdd(out + (size_t)b * EXTV_ + ebev[idx], val);
}

__global__ void copy_k(const float* __restrict__ src, float* __restrict__ dst, int n) {
    int i = blockIdx.x * 256 + threadIdx.x;
    if (i < n) dst[i] = src[i];
}

// ---------------- host-side symbol address helper ----------------
template <typename T>
static void* symaddr_(const T& sym) {
    void* p = nullptr;
    cudaGetSymbolAddress(&p, sym);
    return p;
}

// ---------------- host launcher ----------------
extern "C" void kernel_launch(void* const* d_in, const int* in_sizes, int n_in,
                              void* d_out, int out_size) {
    const int*   y    = (const int*)  d_in[0];
    const float* h0   = (const float*)d_in[1];
    const float* c0   = (const float*)d_in[2];
    const float* enc  = (const float*)d_in[3];
    const float* ct1  = (const float*)d_in[6];
    const int*   ebev = (const int*)  d_in[8];
    const float* cov  = (const float*)d_in[9];

    int wb = 10;
    for (int i = 10; i < n_in; i++) {
        if (in_sizes[i] == 6400000) { wb = i; break; }
    }
    const float* embW = (const float*)d_in[wb + 0];
    const float* xcW  = (const float*)d_in[wb + 1];
    const float* xcb  = (const float*)d_in[wb + 2];
    const float* Wih  = (const float*)d_in[wb + 3];
    const float* Whh  = (const float*)d_in[wb + 4];
    const float* bih  = (const float*)d_in[wb + 5];
    const float* bhh  = (const float*)d_in[wb + 6];
    const float* Wq   = (const float*)d_in[wb + 7];
    const float* Wk   = (const float*)d_in[wb + 8];
    const float* Wv   = (const float*)d_in[wb + 9];
    const float* Wo   = (const float*)d_in[wb + 10];
    const float* pgW  = (const float*)d_in[wb + 11];
    const float* pgb  = (const float*)d_in[wb + 12];
    const float* o1W  = (const float*)d_in[wb + 13];
    const float* o1b  = (const float*)d_in[wb + 14];
    const float* o2W  = (const float*)d_in[wb + 15];
    const float* o2b  = (const float*)d_in[wb + 16];
    float* out = (float*)d_out;
    const bool full = (out_size >= OUT_FULL);

    __nv_bfloat16* p_qkb = (__nv_bfloat16*)symaddr_(g_qkb);
    __nv_bfloat16* p_Ab = (__nv_bfloat16*)symaddr_(g_Ab);
    __nv_bfloat16* p_Bb = (__nv_bfloat16*)symaddr_(g_Bb);
    __nv_bfloat16* p_o2b = (__nv_bfloat16*)symaddr_(g_o2b);
    __nv_bfloat16* p_out1b = (__nv_bfloat16*)symaddr_(g_out1b);
    float* p_wgT  = (float*)symaddr_(g_wgT);
    float* p_xcWT = (float*)symaddr_(g_xcWT);
    float* p_o1WT = (float*)symaddr_(g_o1WT);
    float* p_wvT  = (float*)symaddr_(g_wvT);
    float* p_woT  = (float*)symaddr_(g_woT);
    float* p_cat1 = (float*)symaddr_(g_cat1);
    float* p_x    = (float*)symaddr_(g_x);
    float* p_cat2 = (float*)symaddr_(g_cat2);
    float* p_gates= (float*)symaddr_(g_gates);
    float* p_pool = (float*)symaddr_(g_pooled);
    float* p_ct   = (float*)symaddr_(g_ct);
    float* p_cat3 = (float*)symaddr_(g_cat3);
    float* p_out1 = (float*)symaddr_(g_out1);

    cudaFuncSetAttribute(attn_pool2_k, cudaFuncAttributeMaxDynamicSharedMemorySize, ATTN_SMEM);
    cudaFuncSetAttribute(qk_mma_k, cudaFuncAttributeMaxDynamicSharedMemorySize, QK_SMEM);
    cudaFuncSetAttribute(logits_mma_k, cudaFuncAttributeMaxDynamicSharedMemorySize, QK_SMEM);

    // launches 1-3, then attn_pool2_k at slot 4 (the launch ncu profiles)
    buildAb_k<<<131072, 256>>>(enc, p_Ab);
    buildBb_k<<<2048, 256>>>(Wq, Wk, p_Bb);
    qk_mma_k<<<dim3(16, 512), 128, QK_SMEM>>>(p_Ab, p_Bb, p_qkb);
    attn_pool2_k<<<dim3(8, 512), 256, ATTN_SMEM>>>(p_qkb, enc);

    // weight prep
    build_wgT_k<<<1536, 256>>>(Wih, Whh);
    buildO2b_k<<<(VPAD_ * 256 + 255) / 256, 256>>>(o2W, p_o2b);
    transpose_k<<<dim3(20, 4),   dim3(32, 8)>>>(xcW, p_xcWT, 128, 640);
    transpose_k<<<dim3(24, 8),   dim3(32, 8)>>>(o1W, p_o1WT, 256, 768);
    transpose_k<<<dim3(16, 16),  dim3(32, 8)>>>(Wv, p_wvT, 512, 512);
    transpose_k<<<dim3(16, 16),  dim3(32, 8)>>>(Wo, p_woT, 512, 512);

    // embedding + x projection
    cat1_k<<<1280, 256>>>(ct1, embW, y);
    dense8_k<<<dim3(1, 64), 256>>>(p_cat1, p_xcWT, xcb, nullptr, p_x, 640, 128);

    // LSTM
    cat2_k<<<768, 256>>>(h0);
    dense8_k<<<dim3(4, 64), 256>>>(p_cat2, p_wgT, bih, bhh, p_gates, 384, 1024);
    lstm_k<<<512, 256>>>(c0, full ? out + OFF_H : nullptr, full ? out + OFF_C : nullptr);

    // attention tail: per-head Wv fold + Wo
    wv_head_k<<<dim3(4, 64), 128>>>();
    dense8_k<<<dim3(2, 64), 256>>>(p_pool, p_woT, nullptr, nullptr, p_ct, 512, 512);

    // pointer gate
    pgen_k<<<512, 128>>>(pgW, pgb, full ? out + OFF_PG : nullptr);

    // vocab head (bf16 HMMA logits)
    cat3_k<<<1536, 256>>>();
    dense8_k<<<dim3(1, 64), 256>>>(p_cat3, p_o1WT, o1b, nullptr, p_out1, 768, 256);
    build_out1b_k<<<512, 256>>>();
    zeroZ_k<<<1, 512>>>();
    logits_mma_k<<<dim3(782, 4), 128, QK_SMEM>>>(p_out1b, p_o2b, o2b, out);

    // final distribution
    scale_k<<<25200, 256>>>(out);
    scatter_k<<<1024, 256>>>(ebev, out);

    if (full) {
        copy_k<<<1024, 256>>>(p_ct, out + OFF_CT1, 262144);
        copy_k<<<1024, 256>>>(p_ct, out + OFF_CT2, 262144);
        copy_k<<<256, 256>>>(cov, out + OFF_COV, 65536);
    }
}